// round 5
// baseline (speedup 1.0000x reference)
#include <cuda_runtime.h>
#include <cstdint>

#define Bn 2
#define Sn 2048
#define Dn 1024
#define Hn 16
#define HDn 64
#define BHn (Bn*Hn)
#define Mn (Bn*Sn)       // 4096
#define KSEL 1024        // top-k count

// ---- scratch (static device allocations; no cudaMalloc allowed) ----
__device__ float g_Q[Bn*Hn*Sn*HDn];   // (b,h,s,hd)
__device__ float g_K[Bn*Hn*Sn*HDn];
__device__ float g_V[Bn*Hn*Sn*HDn];
__device__ float g_AV[Bn*Hn*Sn*HDn];

// ---- packed f32x2 helpers (Blackwell FFMA2: 2x fp32 FMA throughput,
//      elementwise fp32 rounding => bitwise-identical to scalar FFMA) ----
__device__ __forceinline__ unsigned long long pack2(float lo, float hi){
    unsigned long long r;
    asm("mov.b64 %0, {%1, %2};" : "=l"(r) : "f"(lo), "f"(hi));
    return r;
}
__device__ __forceinline__ void fma2(unsigned long long &c,
                                     unsigned long long a,
                                     unsigned long long b){
    asm("fma.rn.f32x2 %0, %1, %2, %3;" : "=l"(c) : "l"(a), "l"(b), "l"(c));
}
__device__ __forceinline__ float2 unpack2(unsigned long long v){
    float lo, hi;
    asm("mov.b64 {%0, %1}, %2;" : "=f"(lo), "=f"(hi) : "l"(v));
    return make_float2(lo, hi);
}

// ============================================================
// Kernel 1: batched projections. blockIdx.z selects (A,W,bias,Out).
// C = A @ W^T + bias, scattered to (b,h,s,hd). BK=32, FFMA2 micro.
// ============================================================
__global__ __launch_bounds__(256) void proj3_kernel(
    const float* __restrict__ Aq, const float* __restrict__ Ak, const float* __restrict__ Av,
    const float* __restrict__ Wq, const float* __restrict__ Wk, const float* __restrict__ Wv,
    const float* __restrict__ bq, const float* __restrict__ bk, const float* __restrict__ bv,
    float* __restrict__ Oq, float* __restrict__ Ok, float* __restrict__ Ov)
{
    const float* A; const float* W; const float* bias; float* Out;
    if (blockIdx.z == 0)      { A = Aq; W = Wq; bias = bq; Out = Oq; }
    else if (blockIdx.z == 1) { A = Ak; W = Wk; bias = bk; Out = Ok; }
    else                      { A = Av; W = Wv; bias = bv; Out = Ov; }

    const int BK = 32;
    __shared__ float As[BK][128];
    __shared__ float Bs[BK][128];
    int m0 = blockIdx.y * 128;
    int n0 = blockIdx.x * 128;
    int tid = threadIdx.x;
    int tx = tid & 15, ty = tid >> 4;

    unsigned long long acc2[8][4];
    #pragma unroll
    for (int i=0;i<8;i++)
        #pragma unroll
        for (int p=0;p<4;p++) acc2[i][p]=0ULL;

    for (int k0 = 0; k0 < Dn; k0 += BK) {
        #pragma unroll
        for (int i = 0; i < 4; i++) {
            int idx = tid + i*256;       // 0..1023
            int r  = idx >> 3;           // 0..127
            int c4 = idx & 7;            // 0..7
            float4 v = *(const float4*)(A + (size_t)(m0 + r)*Dn + k0 + c4*4);
            As[c4*4+0][r]=v.x; As[c4*4+1][r]=v.y; As[c4*4+2][r]=v.z; As[c4*4+3][r]=v.w;
        }
        #pragma unroll
        for (int i = 0; i < 4; i++) {
            int idx = tid + i*256;
            int r  = idx >> 3;
            int c4 = idx & 7;
            float4 v = *(const float4*)(W + (size_t)(n0 + r)*Dn + k0 + c4*4);
            Bs[c4*4+0][r]=v.x; Bs[c4*4+1][r]=v.y; Bs[c4*4+2][r]=v.z; Bs[c4*4+3][r]=v.w;
        }
        __syncthreads();
        #pragma unroll
        for (int kk = 0; kk < BK; kk++) {
            ulonglong2 b01 = *(const ulonglong2*)&Bs[kk][tx*8];
            ulonglong2 b23 = *(const ulonglong2*)&Bs[kk][tx*8+4];
            #pragma unroll
            for (int i=0;i<8;i++){
                float a = As[kk][ty*8+i];
                unsigned long long aa = pack2(a, a);
                fma2(acc2[i][0], aa, b01.x);
                fma2(acc2[i][1], aa, b01.y);
                fma2(acc2[i][2], aa, b23.x);
                fma2(acc2[i][3], aa, b23.y);
            }
        }
        __syncthreads();
    }
    #pragma unroll
    for (int i=0;i<8;i++){
        int m = m0 + ty*8 + i;
        int b = m / Sn, s = m % Sn;
        float c[8];
        #pragma unroll
        for (int p=0;p<4;p++){ float2 f = unpack2(acc2[i][p]); c[2*p]=f.x; c[2*p+1]=f.y; }
        #pragma unroll
        for (int j=0;j<8;j++){
            int n = n0 + tx*8 + j;
            int h = n >> 6, hd = n & 63;
            Out[(((size_t)(b*Hn + h))*Sn + s)*HDn + hd] = c[j] + bias[n];
        }
    }
}

// ============================================================
// Kernel 2: scores[bh][q][k] = scale * dot(Q[bh][q], K[bh][k])  (FFMA2)
// ============================================================
__global__ __launch_bounds__(256) void scores_kernel(float* __restrict__ attn)
{
    const int BK = 16;
    __shared__ float As[BK][128];
    __shared__ float Bs[BK][128];
    int bh = blockIdx.z;
    int q0 = blockIdx.y * 128;
    int n0 = blockIdx.x * 128;
    const float* Qb = g_Q + (size_t)bh * Sn * HDn;
    const float* Kb = g_K + (size_t)bh * Sn * HDn;
    float* Cb = attn + (size_t)bh * Sn * Sn;
    int tid = threadIdx.x;
    int tx = tid & 15, ty = tid >> 4;

    unsigned long long acc2[8][4];
    #pragma unroll
    for (int i=0;i<8;i++)
        #pragma unroll
        for (int p=0;p<4;p++) acc2[i][p]=0ULL;

    for (int k0 = 0; k0 < HDn; k0 += BK) {
        #pragma unroll
        for (int i = 0; i < 2; i++) {
            int idx = tid + i*256;
            int r = idx >> 2;
            int c4 = idx & 3;
            float4 v = *(const float4*)(Qb + (size_t)(q0 + r)*HDn + k0 + c4*4);
            As[c4*4+0][r]=v.x; As[c4*4+1][r]=v.y; As[c4*4+2][r]=v.z; As[c4*4+3][r]=v.w;
        }
        #pragma unroll
        for (int i = 0; i < 2; i++) {
            int idx = tid + i*256;
            int r = idx >> 2;
            int c4 = idx & 3;
            float4 v = *(const float4*)(Kb + (size_t)(n0 + r)*HDn + k0 + c4*4);
            Bs[c4*4+0][r]=v.x; Bs[c4*4+1][r]=v.y; Bs[c4*4+2][r]=v.z; Bs[c4*4+3][r]=v.w;
        }
        __syncthreads();
        #pragma unroll
        for (int kk = 0; kk < BK; kk++) {
            ulonglong2 b01 = *(const ulonglong2*)&Bs[kk][tx*8];
            ulonglong2 b23 = *(const ulonglong2*)&Bs[kk][tx*8+4];
            #pragma unroll
            for (int i=0;i<8;i++){
                float a = As[kk][ty*8+i];
                unsigned long long aa = pack2(a, a);
                fma2(acc2[i][0], aa, b01.x);
                fma2(acc2[i][1], aa, b01.y);
                fma2(acc2[i][2], aa, b23.x);
                fma2(acc2[i][3], aa, b23.y);
            }
        }
        __syncthreads();
    }
    const float scale = 0.125f;   // HD^-0.5
    #pragma unroll
    for (int i=0;i<8;i++){
        int q = q0 + ty*8 + i;
        float* rowp = Cb + (size_t)q * Sn + n0 + tx*8;
        float c[8];
        #pragma unroll
        for (int p=0;p<4;p++){ float2 f = unpack2(acc2[i][p]); c[2*p]=f.x; c[2*p+1]=f.y; }
        float4 v0 = make_float4(c[0]*scale, c[1]*scale, c[2]*scale, c[3]*scale);
        float4 v1 = make_float4(c[4]*scale, c[5]*scale, c[6]*scale, c[7]*scale);
        *(float4*)(rowp)     = v0;
        *(float4*)(rowp + 4) = v1;
    }
}

// ============================================================
// Kernel 3: per-WARP exact top-k (4-pass radix select, warp-aggregated
// atomics via match_any) + softmax. One row per warp, in registers.
// ============================================================
__global__ __launch_bounds__(256) void topk_softmax_kernel(float* __restrict__ attn)
{
    __shared__ int hist[8][256];

    const int tid  = threadIdx.x;
    const int lane = tid & 31;
    const int w    = tid >> 5;
    const size_t row = (size_t)blockIdx.x * 8 + w;
    float* rowp = attn + row * (size_t)Sn;
    int* wh = hist[w];

    // load row + precompute order-preserving keys
    float x[64];
    unsigned ku[64];
    #pragma unroll
    for (int j = 0; j < 16; j++) {
        float4 v = *(const float4*)(rowp + lane*4 + j*128);
        x[j*4+0]=v.x; x[j*4+1]=v.y; x[j*4+2]=v.z; x[j*4+3]=v.w;
    }
    float lmax = -3.4e38f;
    #pragma unroll
    for (int e = 0; e < 64; e++) {
        lmax = fmaxf(lmax, x[e]);
        unsigned uf = __float_as_uint(x[e]);
        ku[e] = (uf & 0x80000000u) ? ~uf : (uf | 0x80000000u);
    }
    #pragma unroll
    for (int o=16;o>0;o>>=1) lmax = fmaxf(lmax, __shfl_xor_sync(0xffffffffu, lmax, o));
    float gmax = lmax;

    // 4-pass MSB-first radix select
    unsigned prefix = 0u;
    int r = KSEL;
    #pragma unroll 1
    for (int pass = 3; pass >= 0; pass--) {
        int shift = pass * 8;
        unsigned pmask = (pass == 3) ? 0u : (0xFFFFFFFFu << (shift + 8));
        #pragma unroll
        for (int i = 0; i < 8; i++) wh[lane + i*32] = 0;
        __syncwarp();
        #pragma unroll
        for (int e = 0; e < 64; e++) {
            unsigned u = ku[e];
            bool cand = ((u & pmask) == prefix);
            unsigned act = __ballot_sync(0xffffffffu, cand);
            if (cand) {
                unsigned bin = (u >> shift) & 255u;
                unsigned peers = __match_any_sync(act, bin);
                int leader = __ffs(peers) - 1;
                if (lane == leader) atomicAdd(&wh[bin], __popc(peers));
            }
        }
        __syncwarp();
        int h[8]; int lsum = 0;
        #pragma unroll
        for (int i=0;i<8;i++){ h[i] = wh[lane*8+i]; lsum += h[i]; }
        int incl = lsum;
        #pragma unroll
        for (int o=1;o<32;o<<=1){
            int t2 = __shfl_up_sync(0xffffffffu, incl, o);
            if (lane >= o) incl += t2;
        }
        int total = __shfl_sync(0xffffffffu, incl, 31);
        int A = total - incl;                 // keys in bins above this lane's 8 bins
        int s[9]; s[8] = 0;
        #pragma unroll
        for (int i=7;i>=0;i--) s[i] = s[i+1] + h[i];
        int found = -1, rnew = 0;
        #pragma unroll
        for (int i=0;i<8;i++){
            int ge  = A + s[i];               // count(byte >= bin)
            int gen = A + s[i+1];             // count(byte >= bin+1)
            if (ge >= r && gen < r){ found = i; rnew = r - gen; }
        }
        unsigned ball = __ballot_sync(0xffffffffu, found >= 0);
        int src = __ffs(ball) - 1;
        unsigned bsel = __shfl_sync(0xffffffffu,
                                    (found >= 0) ? (unsigned)(lane*8 + found) : 0u, src);
        r = __shfl_sync(0xffffffffu, rnew, src);
        prefix |= (bsel << shift);
        __syncwarp();
    }
    unsigned thr = prefix;   // exact k-th largest key (ties kept, == reference)

    // masked exp + sum + normalized write
    float lsumf = 0.f;
    #pragma unroll
    for (int e = 0; e < 64; e++) {
        x[e] = (ku[e] >= thr) ? __expf(x[e] - gmax) : 0.f;
        lsumf += x[e];
    }
    #pragma unroll
    for (int o=16;o>0;o>>=1) lsumf += __shfl_xor_sync(0xffffffffu, lsumf, o);
    float inv = 1.f / lsumf;
    #pragma unroll
    for (int j = 0; j < 16; j++) {
        float4 v = make_float4(x[j*4+0]*inv, x[j*4+1]*inv, x[j*4+2]*inv, x[j*4+3]*inv);
        *(float4*)(rowp + lane*4 + j*128) = v;
    }
}

// ============================================================
// Kernel 4: AV[bh][q][d] = sum_k attn[bh][q][k] * V[bh][k][d]  (FFMA2)
// 256x64 tile, 8x8 per thread, As padded stride 257.
// ============================================================
#define AS_STRIDE 257
__global__ __launch_bounds__(256) void av_kernel(const float* __restrict__ attn)
{
    const int BK = 32;
    __shared__ float As[BK*AS_STRIDE];   // [k][m], m stride 257
    __shared__ float Bs[BK][64];         // [k][n]
    int bh = blockIdx.y;
    int m0 = blockIdx.x * 256;
    const float* Arow = attn + (size_t)bh * Sn * Sn;
    const float* Vb   = g_V  + (size_t)bh * Sn * HDn;
    float*       Cb   = g_AV + (size_t)bh * Sn * HDn;
    int tid = threadIdx.x;
    int tx = tid & 7;        // 8 cols of 8
    int ty = tid >> 3;       // 32 rows of 8

    unsigned long long acc2[8][4];
    #pragma unroll
    for (int i=0;i<8;i++)
        #pragma unroll
        for (int p=0;p<4;p++) acc2[i][p]=0ULL;

    for (int k0 = 0; k0 < Sn; k0 += BK) {
        #pragma unroll
        for (int i = 0; i < 8; i++) {
            int idx = tid + i*256;      // 0..2047
            int r  = idx >> 3;          // 0..255 (m)
            int c4 = idx & 7;           // 0..7  (k group)
            float4 v = *(const float4*)(Arow + (size_t)(m0 + r)*Sn + k0 + c4*4);
            As[(c4*4+0)*AS_STRIDE + r]=v.x;
            As[(c4*4+1)*AS_STRIDE + r]=v.y;
            As[(c4*4+2)*AS_STRIDE + r]=v.z;
            As[(c4*4+3)*AS_STRIDE + r]=v.w;
        }
        #pragma unroll
        for (int i = 0; i < 2; i++) {
            int idx = tid + i*256;
            int r = idx >> 4;           // 0..31 (k)
            int c4 = idx & 15;          // 0..15
            float4 v = *(const float4*)(Vb + (size_t)(k0 + r)*HDn + c4*4);
            *(float4*)&Bs[r][c4*4] = v;
        }
        __syncthreads();
        #pragma unroll
        for (int kk = 0; kk < BK; kk++) {
            ulonglong2 b01 = *(const ulonglong2*)&Bs[kk][tx*8];
            ulonglong2 b23 = *(const ulonglong2*)&Bs[kk][tx*8+4];
            #pragma unroll
            for (int i=0;i<8;i++){
                float a = As[kk*AS_STRIDE + ty*8 + i];
                unsigned long long aa = pack2(a, a);
                fma2(acc2[i][0], aa, b01.x);
                fma2(acc2[i][1], aa, b01.y);
                fma2(acc2[i][2], aa, b23.x);
                fma2(acc2[i][3], aa, b23.y);
            }
        }
        __syncthreads();
    }
    #pragma unroll
    for (int i=0;i<8;i++){
        int m = m0 + ty*8 + i;
        float2 f0 = unpack2(acc2[i][0]);
        float2 f1 = unpack2(acc2[i][1]);
        float2 f2 = unpack2(acc2[i][2]);
        float2 f3 = unpack2(acc2[i][3]);
        float4 v0 = make_float4(f0.x, f0.y, f1.x, f1.y);
        float4 v1 = make_float4(f2.x, f2.y, f3.x, f3.y);
        *(float4*)&Cb[(size_t)m*HDn + tx*8]     = v0;
        *(float4*)&Cb[(size_t)m*HDn + tx*8 + 4] = v1;
    }
}

// ============================================================
// Kernel 5: out[m][n] = sum_k AVview[m][k] * Wo[n][k] + bo[n]  (FFMA2, BK=32)
// ============================================================
__global__ __launch_bounds__(256) void outproj_kernel(
    const float* __restrict__ Wo, const float* __restrict__ bo,
    float* __restrict__ out)
{
    const int BK = 32;
    __shared__ float As[BK][128];
    __shared__ float Bs[BK][128];
    int m0 = blockIdx.y * 128;
    int n0 = blockIdx.x * 128;
    int tid = threadIdx.x;
    int tx = tid & 15, ty = tid >> 4;

    unsigned long long acc2[8][4];
    #pragma unroll
    for (int i=0;i<8;i++)
        #pragma unroll
        for (int p=0;p<4;p++) acc2[i][p]=0ULL;

    for (int k0 = 0; k0 < Dn; k0 += BK) {
        int h   = k0 >> 6;          // k0%64 in {0,32}; chunk stays in one head
        int hd0 = k0 & 63;
        #pragma unroll
        for (int i = 0; i < 4; i++) {
            int idx = tid + i*256;
            int r  = idx >> 3;       // 0..127 (m)
            int c4 = idx & 7;        // 0..7 (k group)
            int m = m0 + r;
            int b = m / Sn, s = m % Sn;
            float4 v = *(const float4*)(g_AV + (((size_t)(b*Hn + h))*Sn + s)*HDn + hd0 + c4*4);
            As[c4*4+0][r]=v.x; As[c4*4+1][r]=v.y; As[c4*4+2][r]=v.z; As[c4*4+3][r]=v.w;
        }
        #pragma unroll
        for (int i = 0; i < 4; i++) {
            int idx = tid + i*256;
            int r  = idx >> 3;
            int c4 = idx & 7;
            float4 v = *(const float4*)(Wo + (size_t)(n0 + r)*Dn + k0 + c4*4);
            Bs[c4*4+0][r]=v.x; Bs[c4*4+1][r]=v.y; Bs[c4*4+2][r]=v.z; Bs[c4*4+3][r]=v.w;
        }
        __syncthreads();
        #pragma unroll
        for (int kk = 0; kk < BK; kk++) {
            ulonglong2 b01 = *(const ulonglong2*)&Bs[kk][tx*8];
            ulonglong2 b23 = *(const ulonglong2*)&Bs[kk][tx*8+4];
            #pragma unroll
            for (int i=0;i<8;i++){
                float a = As[kk][ty*8+i];
                unsigned long long aa = pack2(a, a);
                fma2(acc2[i][0], aa, b01.x);
                fma2(acc2[i][1], aa, b01.y);
                fma2(acc2[i][2], aa, b23.x);
                fma2(acc2[i][3], aa, b23.y);
            }
        }
        __syncthreads();
    }
    #pragma unroll
    for (int i=0;i<8;i++){
        int m = m0 + ty*8 + i;
        float* rowp = out + (size_t)m*Dn + n0 + tx*8;
        float c[8];
        #pragma unroll
        for (int p=0;p<4;p++){ float2 f = unpack2(acc2[i][p]); c[2*p]=f.x; c[2*p+1]=f.y; }
        #pragma unroll
        for (int j=0;j<8;j++) rowp[j] = c[j] + bo[n0 + tx*8 + j];
    }
}

// ============================================================
extern "C" void kernel_launch(void* const* d_in, const int* in_sizes, int n_in,
                              void* d_out, int out_size)
{
    const float* query = (const float*)d_in[0];
    const float* key   = (const float*)d_in[1];
    const float* value = (const float*)d_in[2];
    const float* Wq = (const float*)d_in[3];
    const float* bq = (const float*)d_in[4];
    const float* Wk = (const float*)d_in[5];
    const float* bk = (const float*)d_in[6];
    const float* Wv = (const float*)d_in[7];
    const float* bv = (const float*)d_in[8];
    const float* Wo = (const float*)d_in[9];
    const float* bo = (const float*)d_in[10];

    float* out  = (float*)d_out;
    float* attn = out + (size_t)Bn * Sn * Dn;   // second tuple element

    float* gQ;  cudaGetSymbolAddress((void**)&gQ,  g_Q);
    float* gK;  cudaGetSymbolAddress((void**)&gK,  g_K);
    float* gV;  cudaGetSymbolAddress((void**)&gV,  g_V);

    dim3 projGrid(Dn/128, Mn/128, 3);       // (8, 32, 3)
    proj3_kernel<<<projGrid, 256>>>(query, key, value,
                                    Wq, Wk, Wv, bq, bk, bv,
                                    gQ, gK, gV);

    dim3 scoreGrid(Sn/128, Sn/128, BHn);    // (16, 16, 32)
    scores_kernel<<<scoreGrid, 256>>>(attn);

    topk_softmax_kernel<<<BHn * Sn / 8, 256>>>(attn);   // 8192 blocks, 1 row/warp

    dim3 avGrid(Sn/256, BHn);               // (8, 32)
    av_kernel<<<avGrid, 256>>>(attn);

    dim3 outGrid(Dn/128, Mn/128);           // (8, 32)
    outproj_kernel<<<outGrid, 256>>>(Wo, bo, out);
}

// round 6
// speedup vs baseline: 1.9520x; 1.9520x over previous
#include <cuda_runtime.h>
#include <cstdint>

#define Bn 2
#define Sn 2048
#define Dn 1024
#define Hn 16
#define HDn 64
#define BHn (Bn*Hn)
#define Mn (Bn*Sn)       // 4096
#define KSEL 1024        // top-k count

// ---- scratch (static device allocations; no cudaMalloc allowed) ----
__device__ float g_Q[Bn*Hn*Sn*HDn];   // (b,h,s,hd)
__device__ float g_K[Bn*Hn*Sn*HDn];
__device__ float g_V[Bn*Hn*Sn*HDn];
__device__ float g_AV[Bn*Hn*Sn*HDn];

// ============================================================
// Kernel 1: batched projections. blockIdx.z selects (A,W,bias,Out).
// C = A @ W^T + bias, scattered to (b,h,s,hd).  (R4 proven form)
// ============================================================
__global__ __launch_bounds__(256) void proj3_kernel(
    const float* __restrict__ Aq, const float* __restrict__ Ak, const float* __restrict__ Av,
    const float* __restrict__ Wq, const float* __restrict__ Wk, const float* __restrict__ Wv,
    const float* __restrict__ bq, const float* __restrict__ bk, const float* __restrict__ bv,
    float* __restrict__ Oq, float* __restrict__ Ok, float* __restrict__ Ov)
{
    const float* A; const float* W; const float* bias; float* Out;
    if (blockIdx.z == 0)      { A = Aq; W = Wq; bias = bq; Out = Oq; }
    else if (blockIdx.z == 1) { A = Ak; W = Wk; bias = bk; Out = Ok; }
    else                      { A = Av; W = Wv; bias = bv; Out = Ov; }

    const int BK = 16;
    __shared__ float As[BK][128];
    __shared__ float Bs[BK][128];
    int m0 = blockIdx.y * 128;
    int n0 = blockIdx.x * 128;
    int tid = threadIdx.x;
    float acc[8][8];
    #pragma unroll
    for (int i=0;i<8;i++)
        #pragma unroll
        for (int j=0;j<8;j++) acc[i][j]=0.f;

    for (int k0 = 0; k0 < Dn; k0 += BK) {
        #pragma unroll
        for (int i = 0; i < 2; i++) {
            int idx = tid + i*256;
            int r = idx >> 2;
            int c4 = idx & 3;
            float4 v = *(const float4*)(A + (size_t)(m0 + r)*Dn + k0 + c4*4);
            As[c4*4+0][r]=v.x; As[c4*4+1][r]=v.y; As[c4*4+2][r]=v.z; As[c4*4+3][r]=v.w;
        }
        #pragma unroll
        for (int i = 0; i < 2; i++) {
            int idx = tid + i*256;
            int r = idx >> 2;
            int c4 = idx & 3;
            float4 v = *(const float4*)(W + (size_t)(n0 + r)*Dn + k0 + c4*4);
            Bs[c4*4+0][r]=v.x; Bs[c4*4+1][r]=v.y; Bs[c4*4+2][r]=v.z; Bs[c4*4+3][r]=v.w;
        }
        __syncthreads();
        int tx = tid & 15, ty = tid >> 4;
        #pragma unroll
        for (int kk = 0; kk < BK; kk++) {
            float a[8], b[8];
            #pragma unroll
            for (int i=0;i<8;i++) a[i] = As[kk][ty*8+i];
            #pragma unroll
            for (int j=0;j<8;j++) b[j] = Bs[kk][tx*8+j];
            #pragma unroll
            for (int i=0;i<8;i++)
                #pragma unroll
                for (int j=0;j<8;j++) acc[i][j] += a[i]*b[j];
        }
        __syncthreads();
    }
    int tx = tid & 15, ty = tid >> 4;
    #pragma unroll
    for (int i=0;i<8;i++){
        int m = m0 + ty*8 + i;
        int b = m / Sn, s = m % Sn;
        #pragma unroll
        for (int j=0;j<8;j++){
            int n = n0 + tx*8 + j;
            int h = n >> 6, hd = n & 63;
            Out[(((size_t)(b*Hn + h))*Sn + s)*HDn + hd] = acc[i][j] + bias[n];
        }
    }
}

// ============================================================
// Kernel 2: scores[bh][q][k] = scale * dot(Q[bh][q], K[bh][k])
// (R4 proven form)
// ============================================================
__global__ __launch_bounds__(256) void scores_kernel(float* __restrict__ attn)
{
    const int BK = 16;
    __shared__ float As[BK][128];
    __shared__ float Bs[BK][128];
    int bh = blockIdx.z;
    int q0 = blockIdx.y * 128;
    int n0 = blockIdx.x * 128;
    const float* Qb = g_Q + (size_t)bh * Sn * HDn;
    const float* Kb = g_K + (size_t)bh * Sn * HDn;
    float* Cb = attn + (size_t)bh * Sn * Sn;
    int tid = threadIdx.x;
    float acc[8][8];
    #pragma unroll
    for (int i=0;i<8;i++)
        #pragma unroll
        for (int j=0;j<8;j++) acc[i][j]=0.f;

    for (int k0 = 0; k0 < HDn; k0 += BK) {
        #pragma unroll
        for (int i = 0; i < 2; i++) {
            int idx = tid + i*256;
            int r = idx >> 2;
            int c4 = idx & 3;
            float4 v = *(const float4*)(Qb + (size_t)(q0 + r)*HDn + k0 + c4*4);
            As[c4*4+0][r]=v.x; As[c4*4+1][r]=v.y; As[c4*4+2][r]=v.z; As[c4*4+3][r]=v.w;
        }
        #pragma unroll
        for (int i = 0; i < 2; i++) {
            int idx = tid + i*256;
            int r = idx >> 2;
            int c4 = idx & 3;
            float4 v = *(const float4*)(Kb + (size_t)(n0 + r)*HDn + k0 + c4*4);
            Bs[c4*4+0][r]=v.x; Bs[c4*4+1][r]=v.y; Bs[c4*4+2][r]=v.z; Bs[c4*4+3][r]=v.w;
        }
        __syncthreads();
        int tx = tid & 15, ty = tid >> 4;
        #pragma unroll
        for (int kk = 0; kk < BK; kk++) {
            float a[8], b[8];
            #pragma unroll
            for (int i=0;i<8;i++) a[i] = As[kk][ty*8+i];
            #pragma unroll
            for (int j=0;j<8;j++) b[j] = Bs[kk][tx*8+j];
            #pragma unroll
            for (int i=0;i<8;i++)
                #pragma unroll
                for (int j=0;j<8;j++) acc[i][j] += a[i]*b[j];
        }
        __syncthreads();
    }
    const float scale = 0.125f;   // HD^-0.5
    int tx = tid & 15, ty = tid >> 4;
    #pragma unroll
    for (int i=0;i<8;i++){
        int q = q0 + ty*8 + i;
        float* rowp = Cb + (size_t)q * Sn + n0 + tx*8;
        float4 v0 = make_float4(acc[i][0]*scale, acc[i][1]*scale, acc[i][2]*scale, acc[i][3]*scale);
        float4 v1 = make_float4(acc[i][4]*scale, acc[i][5]*scale, acc[i][6]*scale, acc[i][7]*scale);
        *(float4*)(rowp)     = v0;
        *(float4*)(rowp + 4) = v1;
    }
}

// ============================================================
// Kernel 3: per-WARP exact top-k (4-pass radix select) + softmax.
// One row per warp, in registers. Pass 1 (all 2048 keys, exponent-
// concentrated bins) uses warp-aggregated atomics via match_any;
// later passes (few candidates, low contention) use plain atomics.
// ============================================================
__global__ __launch_bounds__(256) void topk_softmax_kernel(float* __restrict__ attn)
{
    __shared__ int hist[8][256];

    const int tid  = threadIdx.x;
    const int lane = tid & 31;
    const int w    = tid >> 5;
    const size_t row = (size_t)blockIdx.x * 8 + w;
    float* rowp = attn + row * (size_t)Sn;
    int* wh = hist[w];

    // load row + precompute order-preserving keys
    float x[64];
    unsigned ku[64];
    #pragma unroll
    for (int j = 0; j < 16; j++) {
        float4 v = *(const float4*)(rowp + lane*4 + j*128);
        x[j*4+0]=v.x; x[j*4+1]=v.y; x[j*4+2]=v.z; x[j*4+3]=v.w;
    }
    float lmax = -3.4e38f;
    #pragma unroll
    for (int e = 0; e < 64; e++) {
        lmax = fmaxf(lmax, x[e]);
        unsigned uf = __float_as_uint(x[e]);
        ku[e] = (uf & 0x80000000u) ? ~uf : (uf | 0x80000000u);
    }
    #pragma unroll
    for (int o=16;o>0;o>>=1) lmax = fmaxf(lmax, __shfl_xor_sync(0xffffffffu, lmax, o));
    float gmax = lmax;

    // 4-pass MSB-first radix select
    unsigned prefix = 0u;
    int r = KSEL;
    #pragma unroll 1
    for (int pass = 3; pass >= 0; pass--) {
        int shift = pass * 8;
        unsigned pmask = (pass == 3) ? 0u : (0xFFFFFFFFu << (shift + 8));
        #pragma unroll
        for (int i = 0; i < 8; i++) wh[lane + i*32] = 0;
        __syncwarp();
        if (pass == 3) {
            // all keys are candidates; bins concentrate -> aggregate
            #pragma unroll
            for (int e = 0; e < 64; e++) {
                unsigned bin = ku[e] >> 24;
                unsigned peers = __match_any_sync(0xffffffffu, bin);
                int leader = __ffs(peers) - 1;
                if (lane == leader) atomicAdd(&wh[bin], __popc(peers));
            }
        } else {
            #pragma unroll
            for (int e = 0; e < 64; e++) {
                unsigned u = ku[e];
                if ((u & pmask) == prefix)
                    atomicAdd(&wh[(u >> shift) & 255u], 1);
            }
        }
        __syncwarp();
        int h[8]; int lsum = 0;
        #pragma unroll
        for (int i=0;i<8;i++){ h[i] = wh[lane*8+i]; lsum += h[i]; }
        int incl = lsum;
        #pragma unroll
        for (int o=1;o<32;o<<=1){
            int t2 = __shfl_up_sync(0xffffffffu, incl, o);
            if (lane >= o) incl += t2;
        }
        int total = __shfl_sync(0xffffffffu, incl, 31);
        int A = total - incl;                 // keys in bins above this lane's 8 bins
        int s[9]; s[8] = 0;
        #pragma unroll
        for (int i=7;i>=0;i--) s[i] = s[i+1] + h[i];
        int found = -1, rnew = 0;
        #pragma unroll
        for (int i=0;i<8;i++){
            int ge  = A + s[i];               // count(byte >= bin)
            int gen = A + s[i+1];             // count(byte >= bin+1)
            if (ge >= r && gen < r){ found = i; rnew = r - gen; }
        }
        unsigned ball = __ballot_sync(0xffffffffu, found >= 0);
        int src = __ffs(ball) - 1;
        unsigned bsel = __shfl_sync(0xffffffffu,
                                    (found >= 0) ? (unsigned)(lane*8 + found) : 0u, src);
        r = __shfl_sync(0xffffffffu, rnew, src);
        prefix |= (bsel << shift);
        __syncwarp();
    }
    unsigned thr = prefix;   // exact k-th largest key (ties kept, == reference)

    // masked exp + sum + normalized write
    float lsumf = 0.f;
    #pragma unroll
    for (int e = 0; e < 64; e++) {
        x[e] = (ku[e] >= thr) ? __expf(x[e] - gmax) : 0.f;
        lsumf += x[e];
    }
    #pragma unroll
    for (int o=16;o>0;o>>=1) lsumf += __shfl_xor_sync(0xffffffffu, lsumf, o);
    float inv = 1.f / lsumf;
    #pragma unroll
    for (int j = 0; j < 16; j++) {
        float4 v = make_float4(x[j*4+0]*inv, x[j*4+1]*inv, x[j*4+2]*inv, x[j*4+3]*inv);
        *(float4*)(rowp + lane*4 + j*128) = v;
    }
}

// ============================================================
// Kernel 4: AV[bh][q][d] = sum_k attn[bh][q][k] * V[bh][k][d]
// 256x64 tile, 8x8 per thread, As padded stride 257. (R4 proven form)
// ============================================================
#define AS_STRIDE 257
__global__ __launch_bounds__(256) void av_kernel(const float* __restrict__ attn)
{
    const int BK = 32;
    __shared__ float As[BK*AS_STRIDE];   // [k][m], m stride 257
    __shared__ float Bs[BK][64];         // [k][n]
    int bh = blockIdx.y;
    int m0 = blockIdx.x * 256;
    const float* Arow = attn + (size_t)bh * Sn * Sn;
    const float* Vb   = g_V  + (size_t)bh * Sn * HDn;
    float*       Cb   = g_AV + (size_t)bh * Sn * HDn;
    int tid = threadIdx.x;
    int tx = tid & 7;        // 8 cols of 8
    int ty = tid >> 3;       // 32 rows of 8
    float acc[8][8];
    #pragma unroll
    for (int i=0;i<8;i++)
        #pragma unroll
        for (int j=0;j<8;j++) acc[i][j]=0.f;

    for (int k0 = 0; k0 < Sn; k0 += BK) {
        #pragma unroll
        for (int i = 0; i < 8; i++) {
            int idx = tid + i*256;      // 0..2047
            int r  = idx >> 3;          // 0..255 (m)
            int c4 = idx & 7;           // 0..7  (k group)
            float4 v = *(const float4*)(Arow + (size_t)(m0 + r)*Sn + k0 + c4*4);
            As[(c4*4+0)*AS_STRIDE + r]=v.x;
            As[(c4*4+1)*AS_STRIDE + r]=v.y;
            As[(c4*4+2)*AS_STRIDE + r]=v.z;
            As[(c4*4+3)*AS_STRIDE + r]=v.w;
        }
        #pragma unroll
        for (int i = 0; i < 2; i++) {
            int idx = tid + i*256;
            int r = idx >> 4;           // 0..31 (k)
            int c4 = idx & 15;          // 0..15
            float4 v = *(const float4*)(Vb + (size_t)(k0 + r)*HDn + c4*4);
            *(float4*)&Bs[r][c4*4] = v;
        }
        __syncthreads();
        #pragma unroll
        for (int kk = 0; kk < BK; kk++) {
            float a[8], b[8];
            #pragma unroll
            for (int i=0;i<8;i++) a[i] = As[kk*AS_STRIDE + ty*8 + i];
            #pragma unroll
            for (int j=0;j<8;j++) b[j] = Bs[kk][tx*8+j];
            #pragma unroll
            for (int i=0;i<8;i++)
                #pragma unroll
                for (int j=0;j<8;j++) acc[i][j] += a[i]*b[j];
        }
        __syncthreads();
    }
    #pragma unroll
    for (int i=0;i<8;i++){
        int m = m0 + ty*8 + i;
        float4 v0 = make_float4(acc[i][0], acc[i][1], acc[i][2], acc[i][3]);
        float4 v1 = make_float4(acc[i][4], acc[i][5], acc[i][6], acc[i][7]);
        *(float4*)&Cb[(size_t)m*HDn + tx*8]     = v0;
        *(float4*)&Cb[(size_t)m*HDn + tx*8 + 4] = v1;
    }
}

// ============================================================
// Kernel 5: out[m][n] = sum_k AVview[m][k] * Wo[n][k] + bo[n]
// (R4 proven form)
// ============================================================
__global__ __launch_bounds__(256) void outproj_kernel(
    const float* __restrict__ Wo, const float* __restrict__ bo,
    float* __restrict__ out)
{
    const int BK = 16;
    __shared__ float As[BK][128];
    __shared__ float Bs[BK][128];
    int m0 = blockIdx.y * 128;
    int n0 = blockIdx.x * 128;
    int tid = threadIdx.x;
    float acc[8][8];
    #pragma unroll
    for (int i=0;i<8;i++)
        #pragma unroll
        for (int j=0;j<8;j++) acc[i][j]=0.f;

    for (int k0 = 0; k0 < Dn; k0 += BK) {
        int h   = k0 >> 6;
        int hd0 = k0 & 63;
        #pragma unroll
        for (int i = 0; i < 2; i++) {
            int idx = tid + i*256;
            int r = idx >> 2;
            int c4 = idx & 3;
            int m = m0 + r;
            int b = m / Sn, s = m % Sn;
            float4 v = *(const float4*)(g_AV + (((size_t)(b*Hn + h))*Sn + s)*HDn + hd0 + c4*4);
            As[c4*4+0][r]=v.x; As[c4*4+1][r]=v.y; As[c4*4+2][r]=v.z; As[c4*4+3][r]=v.w;
        }
        #pragma unroll
        for (int i = 0; i < 2; i++) {
            int idx = tid + i*256;
            int r = idx >> 2;
            int c4 = idx & 3;
            float4 v = *(const float4*)(Wo + (size_t)(n0 + r)*Dn + k0 + c4*4);
            Bs[c4*4+0][r]=v.x; Bs[c4*4+1][r]=v.y; Bs[c4*4+2][r]=v.z; Bs[c4*4+3][r]=v.w;
        }
        __syncthreads();
        int tx = tid & 15, ty = tid >> 4;
        #pragma unroll
        for (int kk = 0; kk < BK; kk++) {
            float a[8], b[8];
            #pragma unroll
            for (int i=0;i<8;i++) a[i] = As[kk][ty*8+i];
            #pragma unroll
            for (int j=0;j<8;j++) b[j] = Bs[kk][tx*8+j];
            #pragma unroll
            for (int i=0;i<8;i++)
                #pragma unroll
                for (int j=0;j<8;j++) acc[i][j] += a[i]*b[j];
        }
        __syncthreads();
    }
    int tx = tid & 15, ty = tid >> 4;
    #pragma unroll
    for (int i=0;i<8;i++){
        int m = m0 + ty*8 + i;
        float* rowp = out + (size_t)m*Dn + n0 + tx*8;
        #pragma unroll
        for (int j=0;j<8;j++) rowp[j] = acc[i][j] + bo[n0 + tx*8 + j];
    }
}

// ============================================================
extern "C" void kernel_launch(void* const* d_in, const int* in_sizes, int n_in,
                              void* d_out, int out_size)
{
    const float* query = (const float*)d_in[0];
    const float* key   = (const float*)d_in[1];
    const float* value = (const float*)d_in[2];
    const float* Wq = (const float*)d_in[3];
    const float* bq = (const float*)d_in[4];
    const float* Wk = (const float*)d_in[5];
    const float* bk = (const float*)d_in[6];
    const float* Wv = (const float*)d_in[7];
    const float* bv = (const float*)d_in[8];
    const float* Wo = (const float*)d_in[9];
    const float* bo = (const float*)d_in[10];

    float* out  = (float*)d_out;
    float* attn = out + (size_t)Bn * Sn * Dn;   // second tuple element

    float* gQ;  cudaGetSymbolAddress((void**)&gQ,  g_Q);
    float* gK;  cudaGetSymbolAddress((void**)&gK,  g_K);
    float* gV;  cudaGetSymbolAddress((void**)&gV,  g_V);

    dim3 projGrid(Dn/128, Mn/128, 3);       // (8, 32, 3)
    proj3_kernel<<<projGrid, 256>>>(query, key, value,
                                    Wq, Wk, Wv, bq, bk, bv,
                                    gQ, gK, gV);

    dim3 scoreGrid(Sn/128, Sn/128, BHn);    // (16, 16, 32)
    scores_kernel<<<scoreGrid, 256>>>(attn);

    topk_softmax_kernel<<<BHn * Sn / 8, 256>>>(attn);   // 8192 blocks, 1 row/warp

    dim3 avGrid(Sn/256, BHn);               // (8, 32)
    av_kernel<<<avGrid, 256>>>(attn);

    dim3 outGrid(Dn/128, Mn/128);           // (8, 32)
    outproj_kernel<<<outGrid, 256>>>(Wo, bo, out);
}

// round 7
// speedup vs baseline: 2.0843x; 1.0677x over previous
#include <cuda_runtime.h>
#include <cstdint>

#define Bn 2
#define Sn 2048
#define Dn 1024
#define Hn 16
#define HDn 64
#define BHn (Bn*Hn)
#define Mn (Bn*Sn)       // 4096
#define KSEL 1024        // top-k count

// ---- scratch (static device allocations; no cudaMalloc allowed) ----
__device__ float g_Q[Bn*Hn*Sn*HDn];   // (b,h,s,hd)
__device__ float g_K[Bn*Hn*Sn*HDn];
__device__ float g_V[Bn*Hn*Sn*HDn];
__device__ float g_AV[Bn*Hn*Sn*HDn];

// order-preserving float->uint key (monotone: a<b <=> key(a)<key(b))
__device__ __forceinline__ unsigned fkey(float f){
    unsigned uf = __float_as_uint(f);
    return (uf & 0x80000000u) ? ~uf : (uf | 0x80000000u);
}

// ============================================================
// Kernel 1: batched projections. blockIdx.z selects (A,W,bias,Out).
// C = A @ W^T + bias, scattered to (b,h,s,hd).  (R4 proven form)
// ============================================================
__global__ __launch_bounds__(256) void proj3_kernel(
    const float* __restrict__ Aq, const float* __restrict__ Ak, const float* __restrict__ Av,
    const float* __restrict__ Wq, const float* __restrict__ Wk, const float* __restrict__ Wv,
    const float* __restrict__ bq, const float* __restrict__ bk, const float* __restrict__ bv,
    float* __restrict__ Oq, float* __restrict__ Ok, float* __restrict__ Ov)
{
    const float* A; const float* W; const float* bias; float* Out;
    if (blockIdx.z == 0)      { A = Aq; W = Wq; bias = bq; Out = Oq; }
    else if (blockIdx.z == 1) { A = Ak; W = Wk; bias = bk; Out = Ok; }
    else                      { A = Av; W = Wv; bias = bv; Out = Ov; }

    const int BK = 16;
    __shared__ float As[BK][128];
    __shared__ float Bs[BK][128];
    int m0 = blockIdx.y * 128;
    int n0 = blockIdx.x * 128;
    int tid = threadIdx.x;
    float acc[8][8];
    #pragma unroll
    for (int i=0;i<8;i++)
        #pragma unroll
        for (int j=0;j<8;j++) acc[i][j]=0.f;

    for (int k0 = 0; k0 < Dn; k0 += BK) {
        #pragma unroll
        for (int i = 0; i < 2; i++) {
            int idx = tid + i*256;
            int r = idx >> 2;
            int c4 = idx & 3;
            float4 v = *(const float4*)(A + (size_t)(m0 + r)*Dn + k0 + c4*4);
            As[c4*4+0][r]=v.x; As[c4*4+1][r]=v.y; As[c4*4+2][r]=v.z; As[c4*4+3][r]=v.w;
        }
        #pragma unroll
        for (int i = 0; i < 2; i++) {
            int idx = tid + i*256;
            int r = idx >> 2;
            int c4 = idx & 3;
            float4 v = *(const float4*)(W + (size_t)(n0 + r)*Dn + k0 + c4*4);
            Bs[c4*4+0][r]=v.x; Bs[c4*4+1][r]=v.y; Bs[c4*4+2][r]=v.z; Bs[c4*4+3][r]=v.w;
        }
        __syncthreads();
        int tx = tid & 15, ty = tid >> 4;
        #pragma unroll
        for (int kk = 0; kk < BK; kk++) {
            float a[8], b[8];
            #pragma unroll
            for (int i=0;i<8;i++) a[i] = As[kk][ty*8+i];
            #pragma unroll
            for (int j=0;j<8;j++) b[j] = Bs[kk][tx*8+j];
            #pragma unroll
            for (int i=0;i<8;i++)
                #pragma unroll
                for (int j=0;j<8;j++) acc[i][j] += a[i]*b[j];
        }
        __syncthreads();
    }
    int tx = tid & 15, ty = tid >> 4;
    #pragma unroll
    for (int i=0;i<8;i++){
        int m = m0 + ty*8 + i;
        int b = m / Sn, s = m % Sn;
        #pragma unroll
        for (int j=0;j<8;j++){
            int n = n0 + tx*8 + j;
            int h = n >> 6, hd = n & 63;
            Out[(((size_t)(b*Hn + h))*Sn + s)*HDn + hd] = acc[i][j] + bias[n];
        }
    }
}

// ============================================================
// Kernel 2: scores[bh][q][k] = scale * dot(Q[bh][q], K[bh][k])
// (R4 proven form)
// ============================================================
__global__ __launch_bounds__(256) void scores_kernel(float* __restrict__ attn)
{
    const int BK = 16;
    __shared__ float As[BK][128];
    __shared__ float Bs[BK][128];
    int bh = blockIdx.z;
    int q0 = blockIdx.y * 128;
    int n0 = blockIdx.x * 128;
    const float* Qb = g_Q + (size_t)bh * Sn * HDn;
    const float* Kb = g_K + (size_t)bh * Sn * HDn;
    float* Cb = attn + (size_t)bh * Sn * Sn;
    int tid = threadIdx.x;
    float acc[8][8];
    #pragma unroll
    for (int i=0;i<8;i++)
        #pragma unroll
        for (int j=0;j<8;j++) acc[i][j]=0.f;

    for (int k0 = 0; k0 < HDn; k0 += BK) {
        #pragma unroll
        for (int i = 0; i < 2; i++) {
            int idx = tid + i*256;
            int r = idx >> 2;
            int c4 = idx & 3;
            float4 v = *(const float4*)(Qb + (size_t)(q0 + r)*HDn + k0 + c4*4);
            As[c4*4+0][r]=v.x; As[c4*4+1][r]=v.y; As[c4*4+2][r]=v.z; As[c4*4+3][r]=v.w;
        }
        #pragma unroll
        for (int i = 0; i < 2; i++) {
            int idx = tid + i*256;
            int r = idx >> 2;
            int c4 = idx & 3;
            float4 v = *(const float4*)(Kb + (size_t)(n0 + r)*HDn + k0 + c4*4);
            Bs[c4*4+0][r]=v.x; Bs[c4*4+1][r]=v.y; Bs[c4*4+2][r]=v.z; Bs[c4*4+3][r]=v.w;
        }
        __syncthreads();
        int tx = tid & 15, ty = tid >> 4;
        #pragma unroll
        for (int kk = 0; kk < BK; kk++) {
            float a[8], b[8];
            #pragma unroll
            for (int i=0;i<8;i++) a[i] = As[kk][ty*8+i];
            #pragma unroll
            for (int j=0;j<8;j++) b[j] = Bs[kk][tx*8+j];
            #pragma unroll
            for (int i=0;i<8;i++)
                #pragma unroll
                for (int j=0;j<8;j++) acc[i][j] += a[i]*b[j];
        }
        __syncthreads();
    }
    const float scale = 0.125f;   // HD^-0.5
    int tx = tid & 15, ty = tid >> 4;
    #pragma unroll
    for (int i=0;i<8;i++){
        int q = q0 + ty*8 + i;
        float* rowp = Cb + (size_t)q * Sn + n0 + tx*8;
        float4 v0 = make_float4(acc[i][0]*scale, acc[i][1]*scale, acc[i][2]*scale, acc[i][3]*scale);
        float4 v1 = make_float4(acc[i][4]*scale, acc[i][5]*scale, acc[i][6]*scale, acc[i][7]*scale);
        *(float4*)(rowp)     = v0;
        *(float4*)(rowp + 4) = v1;
    }
}

// ============================================================
// Kernel 3: per-WARP exact top-k (4-pass radix select) + softmax.
// One row per warp. ONLY x[64] lives in registers; the sortable key
// is recomputed on the fly (3 ALU ops) to avoid register spills.
// ============================================================
__global__ __launch_bounds__(256) void topk_softmax_kernel(float* __restrict__ attn)
{
    __shared__ int hist[8][256];

    const int tid  = threadIdx.x;
    const int lane = tid & 31;
    const int w    = tid >> 5;
    const size_t row = (size_t)blockIdx.x * 8 + w;
    float* rowp = attn + row * (size_t)Sn;
    int* wh = hist[w];

    // load row (only array kept in registers)
    float x[64];
    #pragma unroll
    for (int j = 0; j < 16; j++) {
        float4 v = *(const float4*)(rowp + lane*4 + j*128);
        x[j*4+0]=v.x; x[j*4+1]=v.y; x[j*4+2]=v.z; x[j*4+3]=v.w;
    }
    float lmax = -3.4e38f;
    #pragma unroll
    for (int e = 0; e < 64; e++) lmax = fmaxf(lmax, x[e]);
    #pragma unroll
    for (int o=16;o>0;o>>=1) lmax = fmaxf(lmax, __shfl_xor_sync(0xffffffffu, lmax, o));
    float gmax = lmax;

    // 4-pass MSB-first radix select on recomputed keys
    unsigned prefix = 0u;
    int r = KSEL;
    #pragma unroll 1
    for (int pass = 3; pass >= 0; pass--) {
        int shift = pass * 8;
        unsigned pmask = (pass == 3) ? 0u : (0xFFFFFFFFu << (shift + 8));
        #pragma unroll
        for (int i = 0; i < 8; i++) wh[lane + i*32] = 0;
        __syncwarp();
        #pragma unroll
        for (int e = 0; e < 64; e++) {
            unsigned u = fkey(x[e]);
            if ((u & pmask) == prefix)
                atomicAdd(&wh[(u >> shift) & 255u], 1);
        }
        __syncwarp();
        int h[8]; int lsum = 0;
        #pragma unroll
        for (int i=0;i<8;i++){ h[i] = wh[lane*8+i]; lsum += h[i]; }
        int incl = lsum;
        #pragma unroll
        for (int o=1;o<32;o<<=1){
            int t2 = __shfl_up_sync(0xffffffffu, incl, o);
            if (lane >= o) incl += t2;
        }
        int total = __shfl_sync(0xffffffffu, incl, 31);
        int A = total - incl;                 // keys in bins above this lane's 8 bins
        int s[9]; s[8] = 0;
        #pragma unroll
        for (int i=7;i>=0;i--) s[i] = s[i+1] + h[i];
        int found = -1, rnew = 0;
        #pragma unroll
        for (int i=0;i<8;i++){
            int ge  = A + s[i];               // count(byte >= bin)
            int gen = A + s[i+1];             // count(byte >= bin+1)
            if (ge >= r && gen < r){ found = i; rnew = r - gen; }
        }
        unsigned ball = __ballot_sync(0xffffffffu, found >= 0);
        int src = __ffs(ball) - 1;
        unsigned bsel = __shfl_sync(0xffffffffu,
                                    (found >= 0) ? (unsigned)(lane*8 + found) : 0u, src);
        r = __shfl_sync(0xffffffffu, rnew, src);
        prefix |= (bsel << shift);
        __syncwarp();
    }
    unsigned thr = prefix;   // exact k-th largest key (ties kept, == reference)

    // masked exp + sum + normalized write
    float lsumf = 0.f;
    #pragma unroll
    for (int e = 0; e < 64; e++) {
        x[e] = (fkey(x[e]) >= thr) ? __expf(x[e] - gmax) : 0.f;
        lsumf += x[e];
    }
    #pragma unroll
    for (int o=16;o>0;o>>=1) lsumf += __shfl_xor_sync(0xffffffffu, lsumf, o);
    float inv = 1.f / lsumf;
    #pragma unroll
    for (int j = 0; j < 16; j++) {
        float4 v = make_float4(x[j*4+0]*inv, x[j*4+1]*inv, x[j*4+2]*inv, x[j*4+3]*inv);
        *(float4*)(rowp + lane*4 + j*128) = v;
    }
}

// ============================================================
// Kernel 4: AV[bh][q][d] = sum_k attn[bh][q][k] * V[bh][k][d]
// 256x64 tile, 8x8 per thread, As padded stride 257. (R4 proven form)
// ============================================================
#define AS_STRIDE 257
__global__ __launch_bounds__(256) void av_kernel(const float* __restrict__ attn)
{
    const int BK = 32;
    __shared__ float As[BK*AS_STRIDE];   // [k][m], m stride 257
    __shared__ float Bs[BK][64];         // [k][n]
    int bh = blockIdx.y;
    int m0 = blockIdx.x * 256;
    const float* Arow = attn + (size_t)bh * Sn * Sn;
    const float* Vb   = g_V  + (size_t)bh * Sn * HDn;
    float*       Cb   = g_AV + (size_t)bh * Sn * HDn;
    int tid = threadIdx.x;
    int tx = tid & 7;        // 8 cols of 8
    int ty = tid >> 3;       // 32 rows of 8
    float acc[8][8];
    #pragma unroll
    for (int i=0;i<8;i++)
        #pragma unroll
        for (int j=0;j<8;j++) acc[i][j]=0.f;

    for (int k0 = 0; k0 < Sn; k0 += BK) {
        #pragma unroll
        for (int i = 0; i < 8; i++) {
            int idx = tid + i*256;      // 0..2047
            int r  = idx >> 3;          // 0..255 (m)
            int c4 = idx & 7;           // 0..7  (k group)
            float4 v = *(const float4*)(Arow + (size_t)(m0 + r)*Sn + k0 + c4*4);
            As[(c4*4+0)*AS_STRIDE + r]=v.x;
            As[(c4*4+1)*AS_STRIDE + r]=v.y;
            As[(c4*4+2)*AS_STRIDE + r]=v.z;
            As[(c4*4+3)*AS_STRIDE + r]=v.w;
        }
        #pragma unroll
        for (int i = 0; i < 2; i++) {
            int idx = tid + i*256;
            int r = idx >> 4;           // 0..31 (k)
            int c4 = idx & 15;          // 0..15
            float4 v = *(const float4*)(Vb + (size_t)(k0 + r)*HDn + c4*4);
            *(float4*)&Bs[r][c4*4] = v;
        }
        __syncthreads();
        #pragma unroll
        for (int kk = 0; kk < BK; kk++) {
            float a[8], b[8];
            #pragma unroll
            for (int i=0;i<8;i++) a[i] = As[kk*AS_STRIDE + ty*8 + i];
            #pragma unroll
            for (int j=0;j<8;j++) b[j] = Bs[kk][tx*8+j];
            #pragma unroll
            for (int i=0;i<8;i++)
                #pragma unroll
                for (int j=0;j<8;j++) acc[i][j] += a[i]*b[j];
        }
        __syncthreads();
    }
    #pragma unroll
    for (int i=0;i<8;i++){
        int m = m0 + ty*8 + i;
        float4 v0 = make_float4(acc[i][0], acc[i][1], acc[i][2], acc[i][3]);
        float4 v1 = make_float4(acc[i][4], acc[i][5], acc[i][6], acc[i][7]);
        *(float4*)&Cb[(size_t)m*HDn + tx*8]     = v0;
        *(float4*)&Cb[(size_t)m*HDn + tx*8 + 4] = v1;
    }
}

// ============================================================
// Kernel 5: out[m][n] = sum_k AVview[m][k] * Wo[n][k] + bo[n]
// (R4 proven form)
// ============================================================
__global__ __launch_bounds__(256) void outproj_kernel(
    const float* __restrict__ Wo, const float* __restrict__ bo,
    float* __restrict__ out)
{
    const int BK = 16;
    __shared__ float As[BK][128];
    __shared__ float Bs[BK][128];
    int m0 = blockIdx.y * 128;
    int n0 = blockIdx.x * 128;
    int tid = threadIdx.x;
    float acc[8][8];
    #pragma unroll
    for (int i=0;i<8;i++)
        #pragma unroll
        for (int j=0;j<8;j++) acc[i][j]=0.f;

    for (int k0 = 0; k0 < Dn; k0 += BK) {
        int h   = k0 >> 6;
        int hd0 = k0 & 63;
        #pragma unroll
        for (int i = 0; i < 2; i++) {
            int idx = tid + i*256;
            int r = idx >> 2;
            int c4 = idx & 3;
            int m = m0 + r;
            int b = m / Sn, s = m % Sn;
            float4 v = *(const float4*)(g_AV + (((size_t)(b*Hn + h))*Sn + s)*HDn + hd0 + c4*4);
            As[c4*4+0][r]=v.x; As[c4*4+1][r]=v.y; As[c4*4+2][r]=v.z; As[c4*4+3][r]=v.w;
        }
        #pragma unroll
        for (int i = 0; i < 2; i++) {
            int idx = tid + i*256;
            int r = idx >> 2;
            int c4 = idx & 3;
            float4 v = *(const float4*)(Wo + (size_t)(n0 + r)*Dn + k0 + c4*4);
            Bs[c4*4+0][r]=v.x; Bs[c4*4+1][r]=v.y; Bs[c4*4+2][r]=v.z; Bs[c4*4+3][r]=v.w;
        }
        __syncthreads();
        int tx = tid & 15, ty = tid >> 4;
        #pragma unroll
        for (int kk = 0; kk < BK; kk++) {
            float a[8], b[8];
            #pragma unroll
            for (int i=0;i<8;i++) a[i] = As[kk][ty*8+i];
            #pragma unroll
            for (int j=0;j<8;j++) b[j] = Bs[kk][tx*8+j];
            #pragma unroll
            for (int i=0;i<8;i++)
                #pragma unroll
                for (int j=0;j<8;j++) acc[i][j] += a[i]*b[j];
        }
        __syncthreads();
    }
    int tx = tid & 15, ty = tid >> 4;
    #pragma unroll
    for (int i=0;i<8;i++){
        int m = m0 + ty*8 + i;
        float* rowp = out + (size_t)m*Dn + n0 + tx*8;
        #pragma unroll
        for (int j=0;j<8;j++) rowp[j] = acc[i][j] + bo[n0 + tx*8 + j];
    }
}

// ============================================================
extern "C" void kernel_launch(void* const* d_in, const int* in_sizes, int n_in,
                              void* d_out, int out_size)
{
    const float* query = (const float*)d_in[0];
    const float* key   = (const float*)d_in[1];
    const float* value = (const float*)d_in[2];
    const float* Wq = (const float*)d_in[3];
    const float* bq = (const float*)d_in[4];
    const float* Wk = (const float*)d_in[5];
    const float* bk = (const float*)d_in[6];
    const float* Wv = (const float*)d_in[7];
    const float* bv = (const float*)d_in[8];
    const float* Wo = (const float*)d_in[9];
    const float* bo = (const float*)d_in[10];

    float* out  = (float*)d_out;
    float* attn = out + (size_t)Bn * Sn * Dn;   // second tuple element

    float* gQ;  cudaGetSymbolAddress((void**)&gQ,  g_Q);
    float* gK;  cudaGetSymbolAddress((void**)&gK,  g_K);
    float* gV;  cudaGetSymbolAddress((void**)&gV,  g_V);

    dim3 projGrid(Dn/128, Mn/128, 3);       // (8, 32, 3)
    proj3_kernel<<<projGrid, 256>>>(query, key, value,
                                    Wq, Wk, Wv, bq, bk, bv,
                                    gQ, gK, gV);

    dim3 scoreGrid(Sn/128, Sn/128, BHn);    // (16, 16, 32)
    scores_kernel<<<scoreGrid, 256>>>(attn);

    topk_softmax_kernel<<<BHn * Sn / 8, 256>>>(attn);   // 8192 blocks, 1 row/warp

    dim3 avGrid(Sn/256, BHn);               // (8, 32)
    av_kernel<<<avGrid, 256>>>(attn);

    dim3 outGrid(Dn/128, Mn/128);           // (8, 32)
    outproj_kernel<<<outGrid, 256>>>(Wo, bo, out);
}

// round 8
// speedup vs baseline: 2.2839x; 1.0958x over previous
#include <cuda_runtime.h>
#include <cstdint>

#define Bn 2
#define Sn 2048
#define Dn 1024
#define Hn 16
#define HDn 64
#define BHn (Bn*Hn)
#define Mn (Bn*Sn)       // 4096
#define KSEL 1024        // top-k count

// ---- scratch (static device allocations; no cudaMalloc allowed) ----
__device__ float g_Q[Bn*Hn*Sn*HDn];   // (b,h,s,hd)
__device__ float g_K[Bn*Hn*Sn*HDn];
__device__ float g_V[Bn*Hn*Sn*HDn];
__device__ float g_AV[Bn*Hn*Sn*HDn];

// order-preserving float->uint key (monotone: a<b <=> key(a)<key(b))
__device__ __forceinline__ unsigned fkey(float f){
    unsigned uf = __float_as_uint(f);
    return (uf & 0x80000000u) ? ~uf : (uf | 0x80000000u);
}
__device__ __forceinline__ float finv(unsigned k){
    return __uint_as_float((k & 0x80000000u) ? (k & 0x7FFFFFFFu) : ~k);
}

// ============================================================
// Kernel 1: batched projections. blockIdx.z selects (A,W,bias,Out).
// C = A @ W^T + bias, scattered to (b,h,s,hd).  (R4 proven form)
// ============================================================
__global__ __launch_bounds__(256) void proj3_kernel(
    const float* __restrict__ Aq, const float* __restrict__ Ak, const float* __restrict__ Av,
    const float* __restrict__ Wq, const float* __restrict__ Wk, const float* __restrict__ Wv,
    const float* __restrict__ bq, const float* __restrict__ bk, const float* __restrict__ bv,
    float* __restrict__ Oq, float* __restrict__ Ok, float* __restrict__ Ov)
{
    const float* A; const float* W; const float* bias; float* Out;
    if (blockIdx.z == 0)      { A = Aq; W = Wq; bias = bq; Out = Oq; }
    else if (blockIdx.z == 1) { A = Ak; W = Wk; bias = bk; Out = Ok; }
    else                      { A = Av; W = Wv; bias = bv; Out = Ov; }

    const int BK = 16;
    __shared__ float As[BK][128];
    __shared__ float Bs[BK][128];
    int m0 = blockIdx.y * 128;
    int n0 = blockIdx.x * 128;
    int tid = threadIdx.x;
    float acc[8][8];
    #pragma unroll
    for (int i=0;i<8;i++)
        #pragma unroll
        for (int j=0;j<8;j++) acc[i][j]=0.f;

    for (int k0 = 0; k0 < Dn; k0 += BK) {
        #pragma unroll
        for (int i = 0; i < 2; i++) {
            int idx = tid + i*256;
            int r = idx >> 2;
            int c4 = idx & 3;
            float4 v = *(const float4*)(A + (size_t)(m0 + r)*Dn + k0 + c4*4);
            As[c4*4+0][r]=v.x; As[c4*4+1][r]=v.y; As[c4*4+2][r]=v.z; As[c4*4+3][r]=v.w;
        }
        #pragma unroll
        for (int i = 0; i < 2; i++) {
            int idx = tid + i*256;
            int r = idx >> 2;
            int c4 = idx & 3;
            float4 v = *(const float4*)(W + (size_t)(n0 + r)*Dn + k0 + c4*4);
            Bs[c4*4+0][r]=v.x; Bs[c4*4+1][r]=v.y; Bs[c4*4+2][r]=v.z; Bs[c4*4+3][r]=v.w;
        }
        __syncthreads();
        int tx = tid & 15, ty = tid >> 4;
        #pragma unroll
        for (int kk = 0; kk < BK; kk++) {
            float a[8], b[8];
            #pragma unroll
            for (int i=0;i<8;i++) a[i] = As[kk][ty*8+i];
            #pragma unroll
            for (int j=0;j<8;j++) b[j] = Bs[kk][tx*8+j];
            #pragma unroll
            for (int i=0;i<8;i++)
                #pragma unroll
                for (int j=0;j<8;j++) acc[i][j] += a[i]*b[j];
        }
        __syncthreads();
    }
    int tx = tid & 15, ty = tid >> 4;
    #pragma unroll
    for (int i=0;i<8;i++){
        int m = m0 + ty*8 + i;
        int b = m / Sn, s = m % Sn;
        #pragma unroll
        for (int j=0;j<8;j++){
            int n = n0 + tx*8 + j;
            int h = n >> 6, hd = n & 63;
            Out[(((size_t)(b*Hn + h))*Sn + s)*HDn + hd] = acc[i][j] + bias[n];
        }
    }
}

// ============================================================
// Kernel 2: scores[bh][q][k] = scale * dot(Q[bh][q], K[bh][k])
// (R4 proven form)
// ============================================================
__global__ __launch_bounds__(256) void scores_kernel(float* __restrict__ attn)
{
    const int BK = 16;
    __shared__ float As[BK][128];
    __shared__ float Bs[BK][128];
    int bh = blockIdx.z;
    int q0 = blockIdx.y * 128;
    int n0 = blockIdx.x * 128;
    const float* Qb = g_Q + (size_t)bh * Sn * HDn;
    const float* Kb = g_K + (size_t)bh * Sn * HDn;
    float* Cb = attn + (size_t)bh * Sn * Sn;
    int tid = threadIdx.x;
    float acc[8][8];
    #pragma unroll
    for (int i=0;i<8;i++)
        #pragma unroll
        for (int j=0;j<8;j++) acc[i][j]=0.f;

    for (int k0 = 0; k0 < HDn; k0 += BK) {
        #pragma unroll
        for (int i = 0; i < 2; i++) {
            int idx = tid + i*256;
            int r = idx >> 2;
            int c4 = idx & 3;
            float4 v = *(const float4*)(Qb + (size_t)(q0 + r)*HDn + k0 + c4*4);
            As[c4*4+0][r]=v.x; As[c4*4+1][r]=v.y; As[c4*4+2][r]=v.z; As[c4*4+3][r]=v.w;
        }
        #pragma unroll
        for (int i = 0; i < 2; i++) {
            int idx = tid + i*256;
            int r = idx >> 2;
            int c4 = idx & 3;
            float4 v = *(const float4*)(Kb + (size_t)(n0 + r)*HDn + k0 + c4*4);
            Bs[c4*4+0][r]=v.x; Bs[c4*4+1][r]=v.y; Bs[c4*4+2][r]=v.z; Bs[c4*4+3][r]=v.w;
        }
        __syncthreads();
        int tx = tid & 15, ty = tid >> 4;
        #pragma unroll
        for (int kk = 0; kk < BK; kk++) {
            float a[8], b[8];
            #pragma unroll
            for (int i=0;i<8;i++) a[i] = As[kk][ty*8+i];
            #pragma unroll
            for (int j=0;j<8;j++) b[j] = Bs[kk][tx*8+j];
            #pragma unroll
            for (int i=0;i<8;i++)
                #pragma unroll
                for (int j=0;j<8;j++) acc[i][j] += a[i]*b[j];
        }
        __syncthreads();
    }
    const float scale = 0.125f;   // HD^-0.5
    int tx = tid & 15, ty = tid >> 4;
    #pragma unroll
    for (int i=0;i<8;i++){
        int q = q0 + ty*8 + i;
        float* rowp = Cb + (size_t)q * Sn + n0 + tx*8;
        float4 v0 = make_float4(acc[i][0]*scale, acc[i][1]*scale, acc[i][2]*scale, acc[i][3]*scale);
        float4 v1 = make_float4(acc[i][4]*scale, acc[i][5]*scale, acc[i][6]*scale, acc[i][7]*scale);
        *(float4*)(rowp)     = v0;
        *(float4*)(rowp + 4) = v1;
    }
}

// ============================================================
// Kernel 3: per-WARP exact top-k + softmax, lane-private histograms.
// One row (2048 floats, keys in registers) per warp.
// 6 radix passes (6,6,6,6,6,2 bits). Each lane owns a private 64-bin
// u16 histogram (region = 33 u32 words = 132B, so bank = (lane+word)%32:
// same-bin inserts across lanes land in DISTINCT banks -> clustered
// score distributions are conflict-free). Reduction: 32 conflict-free
// LDS + plain u32 adds (lo-half total < 2^16 -> no carry into hi half).
// ============================================================
#define TKW 8
__global__ __launch_bounds__(256) void topk_softmax_kernel(float* __restrict__ attn)
{
    __shared__ unsigned hist[TKW][32*33];   // per warp: 32 lanes x 33 words

    const int tid  = threadIdx.x;
    const int lane = tid & 31;
    const int w    = tid >> 5;
    const size_t row = (size_t)blockIdx.x * TKW + w;
    float* rowp = attn + row * (size_t)Sn;
    unsigned* H = hist[w];

    // load row as order-preserving keys (registers)
    unsigned ku[64];
    #pragma unroll
    for (int j = 0; j < 16; j++) {
        float4 v = *(const float4*)(rowp + lane*4 + j*128);
        ku[j*4+0]=fkey(v.x); ku[j*4+1]=fkey(v.y); ku[j*4+2]=fkey(v.z); ku[j*4+3]=fkey(v.w);
    }
    unsigned kmax = 0u;
    #pragma unroll
    for (int e = 0; e < 64; e++) kmax = max(kmax, ku[e]);
    #pragma unroll
    for (int o=16;o>0;o>>=1) kmax = max(kmax, __shfl_xor_sync(0xffffffffu, kmax, o));
    float gmax = finv(kmax);

    unsigned prefix = 0u;
    int r = KSEL;
    #pragma unroll 1
    for (int p = 0; p < 6; p++) {
        const int shift = (p < 5) ? (26 - 6*p) : 0;      // 26,20,14,8,2,0
        const int nbit  = (p < 5) ? 6 : 2;
        const unsigned binmask = (1u << nbit) - 1u;
        const int sh2 = shift + nbit;                    // 32,26,20,14,8,2
        const unsigned hm = (sh2 >= 32) ? 0u : (0xFFFFFFFFu << sh2);

        // zero own region
        unsigned* reg = H + lane*33;
        #pragma unroll
        for (int i = 0; i < 33; i++) reg[i] = 0u;
        __syncwarp();
        // insert candidates into lane-private bins (u16 pairs in u32 words)
        #pragma unroll
        for (int e = 0; e < 64; e++) {
            unsigned u = ku[e];
            if ((u & hm) == prefix) {
                unsigned b = (u >> shift) & binmask;
                atomicAdd(&H[lane*33 + (b >> 1)], 1u << (16*(b & 1)));
            }
        }
        __syncwarp();
        // reduce across lanes: lane i owns bins {2i, 2i+1} (word i of each region)
        unsigned acc = 0u;
        #pragma unroll
        for (int l = 0; l < 32; l++) acc += H[l*33 + lane];
        int cLo = (int)(acc & 0xFFFFu);
        int cHi = (int)(acc >> 16);
        int s   = cLo + cHi;
        // suffix sum over lanes (descending bins): suf_i = sum_{j>=i} s_j
        int suf = s;
        #pragma unroll
        for (int o = 1; o < 32; o <<= 1) {
            int v = __shfl_down_sync(0xffffffffu, suf, o);
            if (lane + o < 32) suf += v;
        }
        int geL = suf;           // count(bin >= 2*lane)
        int geH = suf - cLo;     // count(bin >= 2*lane+1)
        int geN = suf - s;       // count(bin >= 2*lane+2)
        int found = -1, rnew = 0;
        if (geH >= r && geN < r) { found = 2*lane + 1; rnew = r - geN; }
        if (geL >= r && geH < r) { found = 2*lane;     rnew = r - geH; }
        unsigned ball = __ballot_sync(0xffffffffu, found >= 0);
        int src = __ffs(ball) - 1;
        unsigned bsel = __shfl_sync(0xffffffffu, (unsigned)found, src);
        r = __shfl_sync(0xffffffffu, rnew, src);
        prefix |= (bsel << shift);
        __syncwarp();
    }
    unsigned thr = prefix;   // exact k-th largest key (ties kept, == reference)

    // masked exp + sum + normalized write (reuse ku[] as float bit store)
    float lsumf = 0.f;
    #pragma unroll
    for (int e = 0; e < 64; e++) {
        unsigned k = ku[e];
        float ex = 0.f;
        if (k >= thr) ex = __expf(finv(k) - gmax);
        ku[e] = __float_as_uint(ex);
        lsumf += ex;
    }
    #pragma unroll
    for (int o=16;o>0;o>>=1) lsumf += __shfl_xor_sync(0xffffffffu, lsumf, o);
    float inv = 1.f / lsumf;
    #pragma unroll
    for (int j = 0; j < 16; j++) {
        float4 v = make_float4(__uint_as_float(ku[j*4+0])*inv,
                               __uint_as_float(ku[j*4+1])*inv,
                               __uint_as_float(ku[j*4+2])*inv,
                               __uint_as_float(ku[j*4+3])*inv);
        *(float4*)(rowp + lane*4 + j*128) = v;
    }
}

// ============================================================
// Kernel 4: AV[bh][q][d] = sum_k attn[bh][q][k] * V[bh][k][d]
// 256x64 tile, 8x8 per thread, As padded stride 257. (R4 proven form)
// ============================================================
#define AS_STRIDE 257
__global__ __launch_bounds__(256) void av_kernel(const float* __restrict__ attn)
{
    const int BK = 32;
    __shared__ float As[BK*AS_STRIDE];   // [k][m], m stride 257
    __shared__ float Bs[BK][64];         // [k][n]
    int bh = blockIdx.y;
    int m0 = blockIdx.x * 256;
    const float* Arow = attn + (size_t)bh * Sn * Sn;
    const float* Vb   = g_V  + (size_t)bh * Sn * HDn;
    float*       Cb   = g_AV + (size_t)bh * Sn * HDn;
    int tid = threadIdx.x;
    int tx = tid & 7;        // 8 cols of 8
    int ty = tid >> 3;       // 32 rows of 8
    float acc[8][8];
    #pragma unroll
    for (int i=0;i<8;i++)
        #pragma unroll
        for (int j=0;j<8;j++) acc[i][j]=0.f;

    for (int k0 = 0; k0 < Sn; k0 += BK) {
        #pragma unroll
        for (int i = 0; i < 8; i++) {
            int idx = tid + i*256;      // 0..2047
            int r  = idx >> 3;          // 0..255 (m)
            int c4 = idx & 7;           // 0..7  (k group)
            float4 v = *(const float4*)(Arow + (size_t)(m0 + r)*Sn + k0 + c4*4);
            As[(c4*4+0)*AS_STRIDE + r]=v.x;
            As[(c4*4+1)*AS_STRIDE + r]=v.y;
            As[(c4*4+2)*AS_STRIDE + r]=v.z;
            As[(c4*4+3)*AS_STRIDE + r]=v.w;
        }
        #pragma unroll
        for (int i = 0; i < 2; i++) {
            int idx = tid + i*256;
            int r = idx >> 4;           // 0..31 (k)
            int c4 = idx & 15;          // 0..15
            float4 v = *(const float4*)(Vb + (size_t)(k0 + r)*HDn + c4*4);
            *(float4*)&Bs[r][c4*4] = v;
        }
        __syncthreads();
        #pragma unroll
        for (int kk = 0; kk < BK; kk++) {
            float a[8], b[8];
            #pragma unroll
            for (int i=0;i<8;i++) a[i] = As[kk*AS_STRIDE + ty*8 + i];
            #pragma unroll
            for (int j=0;j<8;j++) b[j] = Bs[kk][tx*8+j];
            #pragma unroll
            for (int i=0;i<8;i++)
                #pragma unroll
                for (int j=0;j<8;j++) acc[i][j] += a[i]*b[j];
        }
        __syncthreads();
    }
    #pragma unroll
    for (int i=0;i<8;i++){
        int m = m0 + ty*8 + i;
        float4 v0 = make_float4(acc[i][0], acc[i][1], acc[i][2], acc[i][3]);
        float4 v1 = make_float4(acc[i][4], acc[i][5], acc[i][6], acc[i][7]);
        *(float4*)&Cb[(size_t)m*HDn + tx*8]     = v0;
        *(float4*)&Cb[(size_t)m*HDn + tx*8 + 4] = v1;
    }
}

// ============================================================
// Kernel 5: out[m][n] = sum_k AVview[m][k] * Wo[n][k] + bo[n]
// (R4 proven form)
// ============================================================
__global__ __launch_bounds__(256) void outproj_kernel(
    const float* __restrict__ Wo, const float* __restrict__ bo,
    float* __restrict__ out)
{
    const int BK = 16;
    __shared__ float As[BK][128];
    __shared__ float Bs[BK][128];
    int m0 = blockIdx.y * 128;
    int n0 = blockIdx.x * 128;
    int tid = threadIdx.x;
    float acc[8][8];
    #pragma unroll
    for (int i=0;i<8;i++)
        #pragma unroll
        for (int j=0;j<8;j++) acc[i][j]=0.f;

    for (int k0 = 0; k0 < Dn; k0 += BK) {
        int h   = k0 >> 6;
        int hd0 = k0 & 63;
        #pragma unroll
        for (int i = 0; i < 2; i++) {
            int idx = tid + i*256;
            int r = idx >> 2;
            int c4 = idx & 3;
            int m = m0 + r;
            int b = m / Sn, s = m % Sn;
            float4 v = *(const float4*)(g_AV + (((size_t)(b*Hn + h))*Sn + s)*HDn + hd0 + c4*4);
            As[c4*4+0][r]=v.x; As[c4*4+1][r]=v.y; As[c4*4+2][r]=v.z; As[c4*4+3][r]=v.w;
        }
        #pragma unroll
        for (int i = 0; i < 2; i++) {
            int idx = tid + i*256;
            int r = idx >> 2;
            int c4 = idx & 3;
            float4 v = *(const float4*)(Wo + (size_t)(n0 + r)*Dn + k0 + c4*4);
            Bs[c4*4+0][r]=v.x; Bs[c4*4+1][r]=v.y; Bs[c4*4+2][r]=v.z; Bs[c4*4+3][r]=v.w;
        }
        __syncthreads();
        int tx = tid & 15, ty = tid >> 4;
        #pragma unroll
        for (int kk = 0; kk < BK; kk++) {
            float a[8], b[8];
            #pragma unroll
            for (int i=0;i<8;i++) a[i] = As[kk][ty*8+i];
            #pragma unroll
            for (int j=0;j<8;j++) b[j] = Bs[kk][tx*8+j];
            #pragma unroll
            for (int i=0;i<8;i++)
                #pragma unroll
                for (int j=0;j<8;j++) acc[i][j] += a[i]*b[j];
        }
        __syncthreads();
    }
    int tx = tid & 15, ty = tid >> 4;
    #pragma unroll
    for (int i=0;i<8;i++){
        int m = m0 + ty*8 + i;
        float* rowp = out + (size_t)m*Dn + n0 + tx*8;
        #pragma unroll
        for (int j=0;j<8;j++) rowp[j] = acc[i][j] + bo[n0 + tx*8 + j];
    }
}

// ============================================================
extern "C" void kernel_launch(void* const* d_in, const int* in_sizes, int n_in,
                              void* d_out, int out_size)
{
    const float* query = (const float*)d_in[0];
    const float* key   = (const float*)d_in[1];
    const float* value = (const float*)d_in[2];
    const float* Wq = (const float*)d_in[3];
    const float* bq = (const float*)d_in[4];
    const float* Wk = (const float*)d_in[5];
    const float* bk = (const float*)d_in[6];
    const float* Wv = (const float*)d_in[7];
    const float* bv = (const float*)d_in[8];
    const float* Wo = (const float*)d_in[9];
    const float* bo = (const float*)d_in[10];

    float* out  = (float*)d_out;
    float* attn = out + (size_t)Bn * Sn * Dn;   // second tuple element

    float* gQ;  cudaGetSymbolAddress((void**)&gQ,  g_Q);
    float* gK;  cudaGetSymbolAddress((void**)&gK,  g_K);
    float* gV;  cudaGetSymbolAddress((void**)&gV,  g_V);

    dim3 projGrid(Dn/128, Mn/128, 3);       // (8, 32, 3)
    proj3_kernel<<<projGrid, 256>>>(query, key, value,
                                    Wq, Wk, Wv, bq, bk, bv,
                                    gQ, gK, gV);

    dim3 scoreGrid(Sn/128, Sn/128, BHn);    // (16, 16, 32)
    scores_kernel<<<scoreGrid, 256>>>(attn);

    topk_softmax_kernel<<<BHn * Sn / TKW, 256>>>(attn);   // 8192 blocks, 1 row/warp

    dim3 avGrid(Sn/256, BHn);               // (8, 32)
    av_kernel<<<avGrid, 256>>>(attn);

    dim3 outGrid(Dn/128, Mn/128);           // (8, 32)
    outproj_kernel<<<outGrid, 256>>>(Wo, bo, out);
}

// round 9
// speedup vs baseline: 2.5051x; 1.0969x over previous
#include <cuda_runtime.h>
#include <cstdint>

#define Bn 2
#define Sn 2048
#define Dn 1024
#define Hn 16
#define HDn 64
#define BHn (Bn*Hn)
#define Mn (Bn*Sn)       // 4096
#define KSEL 1024        // top-k count

// ---- scratch (static device allocations; no cudaMalloc allowed) ----
__device__ float g_Q[Bn*Hn*Sn*HDn];   // (b,h,s,hd)
__device__ float g_K[Bn*Hn*Sn*HDn];
__device__ float g_V[Bn*Hn*Sn*HDn];
__device__ float g_AV[Bn*Hn*Sn*HDn];

// order-preserving float->uint key
__device__ __forceinline__ unsigned fkey(float f){
    unsigned uf = __float_as_uint(f);
    return (uf & 0x80000000u) ? ~uf : (uf | 0x80000000u);
}
__device__ __forceinline__ float finv(unsigned k){
    return __uint_as_float((k & 0x80000000u) ? (k & 0x7FFFFFFFu) : ~k);
}

// ---- tf32x3 helpers: fp32-accurate GEMM on tensor pipe ----
__device__ __forceinline__ void tf32split(float x, unsigned &hi, unsigned &lo){
    unsigned h; asm("cvt.rna.tf32.f32 %0, %1;" : "=r"(h) : "f"(x));
    float hf = __uint_as_float(h);
    asm("cvt.rna.tf32.f32 %0, %1;" : "=r"(lo) : "f"(x - hf));
    hi = h;
}
__device__ __forceinline__ void mma_tf32(float* c, const unsigned* a, const unsigned* b){
    asm volatile("mma.sync.aligned.m16n8k8.row.col.f32.tf32.tf32.f32 "
        "{%0,%1,%2,%3}, {%4,%5,%6,%7}, {%8,%9}, {%0,%1,%2,%3};"
        : "+f"(c[0]), "+f"(c[1]), "+f"(c[2]), "+f"(c[3])
        : "r"(a[0]), "r"(a[1]), "r"(a[2]), "r"(a[3]), "r"(b[0]), "r"(b[1]));
}

// ============================================================
// Kernel 1: batched projections (R4 proven form)
// ============================================================
__global__ __launch_bounds__(256) void proj3_kernel(
    const float* __restrict__ Aq, const float* __restrict__ Ak, const float* __restrict__ Av,
    const float* __restrict__ Wq, const float* __restrict__ Wk, const float* __restrict__ Wv,
    const float* __restrict__ bq, const float* __restrict__ bk, const float* __restrict__ bv,
    float* __restrict__ Oq, float* __restrict__ Ok, float* __restrict__ Ov)
{
    const float* A; const float* W; const float* bias; float* Out;
    if (blockIdx.z == 0)      { A = Aq; W = Wq; bias = bq; Out = Oq; }
    else if (blockIdx.z == 1) { A = Ak; W = Wk; bias = bk; Out = Ok; }
    else                      { A = Av; W = Wv; bias = bv; Out = Ov; }

    const int BK = 16;
    __shared__ float As[BK][128];
    __shared__ float Bs[BK][128];
    int m0 = blockIdx.y * 128;
    int n0 = blockIdx.x * 128;
    int tid = threadIdx.x;
    float acc[8][8];
    #pragma unroll
    for (int i=0;i<8;i++)
        #pragma unroll
        for (int j=0;j<8;j++) acc[i][j]=0.f;

    for (int k0 = 0; k0 < Dn; k0 += BK) {
        #pragma unroll
        for (int i = 0; i < 2; i++) {
            int idx = tid + i*256;
            int r = idx >> 2;
            int c4 = idx & 3;
            float4 v = *(const float4*)(A + (size_t)(m0 + r)*Dn + k0 + c4*4);
            As[c4*4+0][r]=v.x; As[c4*4+1][r]=v.y; As[c4*4+2][r]=v.z; As[c4*4+3][r]=v.w;
        }
        #pragma unroll
        for (int i = 0; i < 2; i++) {
            int idx = tid + i*256;
            int r = idx >> 2;
            int c4 = idx & 3;
            float4 v = *(const float4*)(W + (size_t)(n0 + r)*Dn + k0 + c4*4);
            Bs[c4*4+0][r]=v.x; Bs[c4*4+1][r]=v.y; Bs[c4*4+2][r]=v.z; Bs[c4*4+3][r]=v.w;
        }
        __syncthreads();
        int tx = tid & 15, ty = tid >> 4;
        #pragma unroll
        for (int kk = 0; kk < BK; kk++) {
            float a[8], b[8];
            #pragma unroll
            for (int i=0;i<8;i++) a[i] = As[kk][ty*8+i];
            #pragma unroll
            for (int j=0;j<8;j++) b[j] = Bs[kk][tx*8+j];
            #pragma unroll
            for (int i=0;i<8;i++)
                #pragma unroll
                for (int j=0;j<8;j++) acc[i][j] += a[i]*b[j];
        }
        __syncthreads();
    }
    int tx = tid & 15, ty = tid >> 4;
    #pragma unroll
    for (int i=0;i<8;i++){
        int m = m0 + ty*8 + i;
        int b = m / Sn, s = m % Sn;
        #pragma unroll
        for (int j=0;j<8;j++){
            int n = n0 + tx*8 + j;
            int h = n >> 6, hd = n & 63;
            Out[(((size_t)(b*Hn + h))*Sn + s)*HDn + hd] = acc[i][j] + bias[n];
        }
    }
}

// ============================================================
// Kernel 2: scores via tf32x3 tensor MMA.
// Block: 128q x 128k for one bh. 8 warps in 4x2; warp = 32q x 64k.
// smem tiles stride 72 (==8 mod 32 -> conflict-free fragment LDS).
// ============================================================
#define TS 72
__global__ __launch_bounds__(256) void scores_mma_kernel(float* __restrict__ attn)
{
    extern __shared__ float sm[];
    float* Qs = sm;              // 128 x TS (cols 0..63 used)
    float* Ks = sm + 128*TS;     // 128 x TS
    int bh = blockIdx.z;
    int q0 = blockIdx.y * 128;
    int n0 = blockIdx.x * 128;
    const float* Qb = g_Q + (size_t)bh*Sn*HDn;
    const float* Kb = g_K + (size_t)bh*Sn*HDn;
    float* Cb = attn + (size_t)bh*Sn*Sn;
    int tid = threadIdx.x;

    #pragma unroll
    for (int i = 0; i < 8; i++){
        int idx = tid + i*256;       // 0..2047
        int r = idx >> 4; int c4 = idx & 15;
        float4 v = *(const float4*)(Qb + (size_t)(q0+r)*HDn + c4*4);
        *(float4*)&Qs[r*TS + c4*4] = v;
        float4 u = *(const float4*)(Kb + (size_t)(n0+r)*HDn + c4*4);
        *(float4*)&Ks[r*TS + c4*4] = u;
    }
    __syncthreads();

    int lane = tid & 31, w = tid >> 5;
    int mb = (w >> 1) * 32;          // warp q offset
    int nb = (w & 1) * 64;           // warp k offset
    int g = lane >> 2, c = lane & 3;

    float acc[2][8][4];
    #pragma unroll
    for (int mf=0;mf<2;mf++)
        #pragma unroll
        for (int nf=0;nf<8;nf++)
            #pragma unroll
            for (int e=0;e<4;e++) acc[mf][nf][e]=0.f;

    #pragma unroll
    for (int ks = 0; ks < 8; ks++){
        unsigned ah[2][4], al[2][4];
        #pragma unroll
        for (int mf=0; mf<2; mf++){
            const float* base = &Qs[(mb+mf*16)*TS + ks*8];
            tf32split(base[ g     *TS + c    ], ah[mf][0], al[mf][0]);
            tf32split(base[(g+8)  *TS + c    ], ah[mf][1], al[mf][1]);
            tf32split(base[ g     *TS + c + 4], ah[mf][2], al[mf][2]);
            tf32split(base[(g+8)  *TS + c + 4], ah[mf][3], al[mf][3]);
        }
        #pragma unroll
        for (int nf=0; nf<8; nf++){
            const float* base = &Ks[(nb+nf*8)*TS + ks*8];
            unsigned bh_[2], bl_[2];
            tf32split(base[g*TS + c    ], bh_[0], bl_[0]);
            tf32split(base[g*TS + c + 4], bh_[1], bl_[1]);
            #pragma unroll
            for (int mf=0; mf<2; mf++){
                mma_tf32(acc[mf][nf], ah[mf], bh_);
                mma_tf32(acc[mf][nf], ah[mf], bl_);
                mma_tf32(acc[mf][nf], al[mf], bh_);
            }
        }
    }

    const float scale = 0.125f;      // HD^-0.5
    #pragma unroll
    for (int mf=0; mf<2; mf++){
        #pragma unroll
        for (int nf=0; nf<8; nf++){
            int row = q0 + mb + mf*16 + g;
            int col = n0 + nb + nf*8 + 2*c;
            float* p = Cb + (size_t)row*Sn + col;
            float2 v0 = make_float2(acc[mf][nf][0]*scale, acc[mf][nf][1]*scale);
            float2 v1 = make_float2(acc[mf][nf][2]*scale, acc[mf][nf][3]*scale);
            *(float2*)p = v0;
            *(float2*)(p + (size_t)8*Sn) = v1;
        }
    }
}

// ============================================================
// Kernel 3: per-WARP exact top-k + softmax (R8 proven: lane-private hists)
// ============================================================
#define TKW 8
__global__ __launch_bounds__(256) void topk_softmax_kernel(float* __restrict__ attn)
{
    __shared__ unsigned hist[TKW][32*33];

    const int tid  = threadIdx.x;
    const int lane = tid & 31;
    const int w    = tid >> 5;
    const size_t row = (size_t)blockIdx.x * TKW + w;
    float* rowp = attn + row * (size_t)Sn;
    unsigned* H = hist[w];

    unsigned ku[64];
    #pragma unroll
    for (int j = 0; j < 16; j++) {
        float4 v = *(const float4*)(rowp + lane*4 + j*128);
        ku[j*4+0]=fkey(v.x); ku[j*4+1]=fkey(v.y); ku[j*4+2]=fkey(v.z); ku[j*4+3]=fkey(v.w);
    }
    unsigned kmax = 0u;
    #pragma unroll
    for (int e = 0; e < 64; e++) kmax = max(kmax, ku[e]);
    #pragma unroll
    for (int o=16;o>0;o>>=1) kmax = max(kmax, __shfl_xor_sync(0xffffffffu, kmax, o));
    float gmax = finv(kmax);

    unsigned prefix = 0u;
    int r = KSEL;
    #pragma unroll 1
    for (int p = 0; p < 6; p++) {
        const int shift = (p < 5) ? (26 - 6*p) : 0;
        const int nbit  = (p < 5) ? 6 : 2;
        const unsigned binmask = (1u << nbit) - 1u;
        const int sh2 = shift + nbit;
        const unsigned hm = (sh2 >= 32) ? 0u : (0xFFFFFFFFu << sh2);

        unsigned* reg = H + lane*33;
        #pragma unroll
        for (int i = 0; i < 33; i++) reg[i] = 0u;
        __syncwarp();
        #pragma unroll
        for (int e = 0; e < 64; e++) {
            unsigned u = ku[e];
            if ((u & hm) == prefix) {
                unsigned b = (u >> shift) & binmask;
                atomicAdd(&H[lane*33 + (b >> 1)], 1u << (16*(b & 1)));
            }
        }
        __syncwarp();
        unsigned acc = 0u;
        #pragma unroll
        for (int l = 0; l < 32; l++) acc += H[l*33 + lane];
        int cLo = (int)(acc & 0xFFFFu);
        int cHi = (int)(acc >> 16);
        int s   = cLo + cHi;
        int suf = s;
        #pragma unroll
        for (int o = 1; o < 32; o <<= 1) {
            int v = __shfl_down_sync(0xffffffffu, suf, o);
            if (lane + o < 32) suf += v;
        }
        int geL = suf;
        int geH = suf - cLo;
        int geN = suf - s;
        int found = -1, rnew = 0;
        if (geH >= r && geN < r) { found = 2*lane + 1; rnew = r - geN; }
        if (geL >= r && geH < r) { found = 2*lane;     rnew = r - geH; }
        unsigned ball = __ballot_sync(0xffffffffu, found >= 0);
        int src = __ffs(ball) - 1;
        unsigned bsel = __shfl_sync(0xffffffffu, (unsigned)found, src);
        r = __shfl_sync(0xffffffffu, rnew, src);
        prefix |= (bsel << shift);
        __syncwarp();
    }
    unsigned thr = prefix;

    float lsumf = 0.f;
    #pragma unroll
    for (int e = 0; e < 64; e++) {
        unsigned k = ku[e];
        float ex = 0.f;
        if (k >= thr) ex = __expf(finv(k) - gmax);
        ku[e] = __float_as_uint(ex);
        lsumf += ex;
    }
    #pragma unroll
    for (int o=16;o>0;o>>=1) lsumf += __shfl_xor_sync(0xffffffffu, lsumf, o);
    float inv = 1.f / lsumf;
    #pragma unroll
    for (int j = 0; j < 16; j++) {
        float4 v = make_float4(__uint_as_float(ku[j*4+0])*inv,
                               __uint_as_float(ku[j*4+1])*inv,
                               __uint_as_float(ku[j*4+2])*inv,
                               __uint_as_float(ku[j*4+3])*inv);
        *(float4*)(rowp + lane*4 + j*128) = v;
    }
}

// ============================================================
// Kernel 4: AV via tf32x3 tensor MMA.
// Block: 128q x 64d, k-loop 2048 in 64-chunks. 8 warps 4x2; warp 32q x 32d.
// ============================================================
__global__ __launch_bounds__(256) void av_mma_kernel(const float* __restrict__ attn)
{
    extern __shared__ float sm[];
    float* As_ = sm;              // 128 x TS (k cols 0..63)
    float* Vs  = sm + 128*TS;     // 64 x TS (d cols 0..63)
    int bh = blockIdx.y;
    int m0 = blockIdx.x * 128;
    const float* Ab = attn + (size_t)bh*Sn*Sn;
    const float* Vb = g_V + (size_t)bh*Sn*HDn;
    float* Cb = g_AV + (size_t)bh*Sn*HDn;
    int tid = threadIdx.x;
    int lane = tid & 31, w = tid >> 5;
    int mb = (w >> 1) * 32;
    int nb = (w & 1) * 32;
    int g = lane >> 2, c = lane & 3;

    float acc[2][4][4];
    #pragma unroll
    for (int mf=0;mf<2;mf++)
        #pragma unroll
        for (int nf=0;nf<4;nf++)
            #pragma unroll
            for (int e=0;e<4;e++) acc[mf][nf][e]=0.f;

    for (int k0 = 0; k0 < Sn; k0 += 64) {
        #pragma unroll
        for (int i = 0; i < 8; i++){
            int idx = tid + i*256;        // 0..2047
            int r = idx >> 4; int c4 = idx & 15;
            float4 v = *(const float4*)(Ab + (size_t)(m0+r)*Sn + k0 + c4*4);
            *(float4*)&As_[r*TS + c4*4] = v;
        }
        #pragma unroll
        for (int i = 0; i < 4; i++){
            int idx = tid + i*256;        // 0..1023
            int r = idx >> 4; int c4 = idx & 15;
            float4 v = *(const float4*)(Vb + (size_t)(k0+r)*HDn + c4*4);
            *(float4*)&Vs[r*TS + c4*4] = v;
        }
        __syncthreads();

        #pragma unroll
        for (int ks = 0; ks < 8; ks++){
            unsigned ah[2][4], al[2][4];
            #pragma unroll
            for (int mf=0; mf<2; mf++){
                const float* base = &As_[(mb+mf*16)*TS + ks*8];
                tf32split(base[ g   *TS + c    ], ah[mf][0], al[mf][0]);
                tf32split(base[(g+8)*TS + c    ], ah[mf][1], al[mf][1]);
                tf32split(base[ g   *TS + c + 4], ah[mf][2], al[mf][2]);
                tf32split(base[(g+8)*TS + c + 4], ah[mf][3], al[mf][3]);
            }
            #pragma unroll
            for (int nf=0; nf<4; nf++){
                // B[n=d][k]: element = V[k][d] = Vs[k*TS + d]
                unsigned bh_[2], bl_[2];
                tf32split(Vs[(ks*8 + c    )*TS + nb + nf*8 + g], bh_[0], bl_[0]);
                tf32split(Vs[(ks*8 + c + 4)*TS + nb + nf*8 + g], bh_[1], bl_[1]);
                #pragma unroll
                for (int mf=0; mf<2; mf++){
                    mma_tf32(acc[mf][nf], ah[mf], bh_);
                    mma_tf32(acc[mf][nf], ah[mf], bl_);
                    mma_tf32(acc[mf][nf], al[mf], bh_);
                }
            }
        }
        __syncthreads();
    }

    #pragma unroll
    for (int mf=0; mf<2; mf++){
        #pragma unroll
        for (int nf=0; nf<4; nf++){
            int row = m0 + mb + mf*16 + g;
            int col = nb + nf*8 + 2*c;
            float* p = Cb + (size_t)row*HDn + col;
            *(float2*)p = make_float2(acc[mf][nf][0], acc[mf][nf][1]);
            *(float2*)(p + (size_t)8*HDn) = make_float2(acc[mf][nf][2], acc[mf][nf][3]);
        }
    }
}

// ============================================================
// Kernel 5: out projection (R4 proven form)
// ============================================================
__global__ __launch_bounds__(256) void outproj_kernel(
    const float* __restrict__ Wo, const float* __restrict__ bo,
    float* __restrict__ out)
{
    const int BK = 16;
    __shared__ float As[BK][128];
    __shared__ float Bs[BK][128];
    int m0 = blockIdx.y * 128;
    int n0 = blockIdx.x * 128;
    int tid = threadIdx.x;
    float acc[8][8];
    #pragma unroll
    for (int i=0;i<8;i++)
        #pragma unroll
        for (int j=0;j<8;j++) acc[i][j]=0.f;

    for (int k0 = 0; k0 < Dn; k0 += BK) {
        int h   = k0 >> 6;
        int hd0 = k0 & 63;
        #pragma unroll
        for (int i = 0; i < 2; i++) {
            int idx = tid + i*256;
            int r = idx >> 2;
            int c4 = idx & 3;
            int m = m0 + r;
            int b = m / Sn, s = m % Sn;
            float4 v = *(const float4*)(g_AV + (((size_t)(b*Hn + h))*Sn + s)*HDn + hd0 + c4*4);
            As[c4*4+0][r]=v.x; As[c4*4+1][r]=v.y; As[c4*4+2][r]=v.z; As[c4*4+3][r]=v.w;
        }
        #pragma unroll
        for (int i = 0; i < 2; i++) {
            int idx = tid + i*256;
            int r = idx >> 2;
            int c4 = idx & 3;
            float4 v = *(const float4*)(Wo + (size_t)(n0 + r)*Dn + k0 + c4*4);
            Bs[c4*4+0][r]=v.x; Bs[c4*4+1][r]=v.y; Bs[c4*4+2][r]=v.z; Bs[c4*4+3][r]=v.w;
        }
        __syncthreads();
        int tx = tid & 15, ty = tid >> 4;
        #pragma unroll
        for (int kk = 0; kk < BK; kk++) {
            float a[8], b[8];
            #pragma unroll
            for (int i=0;i<8;i++) a[i] = As[kk][ty*8+i];
            #pragma unroll
            for (int j=0;j<8;j++) b[j] = Bs[kk][tx*8+j];
            #pragma unroll
            for (int i=0;i<8;i++)
                #pragma unroll
                for (int j=0;j<8;j++) acc[i][j] += a[i]*b[j];
        }
        __syncthreads();
    }
    int tx = tid & 15, ty = tid >> 4;
    #pragma unroll
    for (int i=0;i<8;i++){
        int m = m0 + ty*8 + i;
        float* rowp = out + (size_t)m*Dn + n0 + tx*8;
        #pragma unroll
        for (int j=0;j<8;j++) rowp[j] = acc[i][j] + bo[n0 + tx*8 + j];
    }
}

// ============================================================
extern "C" void kernel_launch(void* const* d_in, const int* in_sizes, int n_in,
                              void* d_out, int out_size)
{
    const float* query = (const float*)d_in[0];
    const float* key   = (const float*)d_in[1];
    const float* value = (const float*)d_in[2];
    const float* Wq = (const float*)d_in[3];
    const float* bq = (const float*)d_in[4];
    const float* Wk = (const float*)d_in[5];
    const float* bk = (const float*)d_in[6];
    const float* Wv = (const float*)d_in[7];
    const float* bv = (const float*)d_in[8];
    const float* Wo = (const float*)d_in[9];
    const float* bo = (const float*)d_in[10];

    float* out  = (float*)d_out;
    float* attn = out + (size_t)Bn * Sn * Dn;

    float* gQ;  cudaGetSymbolAddress((void**)&gQ,  g_Q);
    float* gK;  cudaGetSymbolAddress((void**)&gK,  g_K);
    float* gV;  cudaGetSymbolAddress((void**)&gV,  g_V);

    const int scoresSmem = 2*128*TS*4;          // 73728 B
    const int avSmem     = (128+64)*TS*4;       // 55296 B
    cudaFuncSetAttribute(scores_mma_kernel,
        cudaFuncAttributeMaxDynamicSharedMemorySize, scoresSmem);
    cudaFuncSetAttribute(av_mma_kernel,
        cudaFuncAttributeMaxDynamicSharedMemorySize, avSmem);

    dim3 projGrid(Dn/128, Mn/128, 3);
    proj3_kernel<<<projGrid, 256>>>(query, key, value,
                                    Wq, Wk, Wv, bq, bk, bv,
                                    gQ, gK, gV);

    dim3 scoreGrid(Sn/128, Sn/128, BHn);        // (16,16,32)
    scores_mma_kernel<<<scoreGrid, 256, scoresSmem>>>(attn);

    topk_softmax_kernel<<<BHn * Sn / TKW, 256>>>(attn);

    dim3 avGrid(Sn/128, BHn);                   // (16,32)
    av_mma_kernel<<<avGrid, 256, avSmem>>>(attn);

    dim3 outGrid(Dn/128, Mn/128);
    outproj_kernel<<<outGrid, 256>>>(Wo, bo, out);
}

// round 11
// speedup vs baseline: 2.7358x; 1.0921x over previous
#include <cuda_runtime.h>
#include <cstdint>

#define Bn 2
#define Sn 2048
#define Dn 1024
#define Hn 16
#define HDn 64
#define BHn (Bn*Hn)
#define Mn (Bn*Sn)       // 4096
#define KSEL 1024        // top-k count

// ---- scratch (static device allocations; no cudaMalloc allowed) ----
__device__ float g_Q[Bn*Hn*Sn*HDn];   // (b,h,s,hd)
__device__ float g_K[Bn*Hn*Sn*HDn];
__device__ float g_V[Bn*Hn*Sn*HDn];
__device__ float g_AV[Bn*Hn*Sn*HDn];

// order-preserving float->uint key
__device__ __forceinline__ unsigned fkey(float f){
    unsigned uf = __float_as_uint(f);
    return (uf & 0x80000000u) ? ~uf : (uf | 0x80000000u);
}
__device__ __forceinline__ float finv(unsigned k){
    return __uint_as_float((k & 0x80000000u) ? (k & 0x7FFFFFFFu) : ~k);
}

// ---- tf32x3 helpers ----
__device__ __forceinline__ void tf32split(float x, unsigned &hi, unsigned &lo){
    unsigned h; asm("cvt.rna.tf32.f32 %0, %1;" : "=r"(h) : "f"(x));
    float hf = __uint_as_float(h);
    asm("cvt.rna.tf32.f32 %0, %1;" : "=r"(lo) : "f"(x - hf));
    hi = h;
}
__device__ __forceinline__ void split4(float4 v, uint4 &hi, uint4 &lo){
    tf32split(v.x, hi.x, lo.x);
    tf32split(v.y, hi.y, lo.y);
    tf32split(v.z, hi.z, lo.z);
    tf32split(v.w, hi.w, lo.w);
}
__device__ __forceinline__ void mma_tf32(float* c, const unsigned* a, const unsigned* b){
    asm volatile("mma.sync.aligned.m16n8k8.row.col.f32.tf32.tf32.f32 "
        "{%0,%1,%2,%3}, {%4,%5,%6,%7}, {%8,%9}, {%0,%1,%2,%3};"
        : "+f"(c[0]), "+f"(c[1]), "+f"(c[2]), "+f"(c[3])
        : "r"(a[0]), "r"(a[1]), "r"(a[2]), "r"(a[3]), "r"(b[0]), "r"(b[1]));
}

// tile strides (in u32 words)
#define TSA 68   // row-pattern tiles: (g*4+c)%32 distinct -> conflict-free
#define TSV 72   // transposed-pattern (av V): (c*8+g)%32 distinct -> conflict-free

// warp-level tf32x3 micro: 32m x 32n, one 64-k chunk from hi/lo tiles.
__device__ __forceinline__ void mma_chunk_rowB(
    float acc[2][4][4], const unsigned* Ah, const unsigned* Al,
    const unsigned* Bh, const unsigned* Bl, int mb, int nb, int g, int c)
{
    #pragma unroll
    for (int ks = 0; ks < 8; ks++){
        unsigned ah[2][4], al[2][4];
        #pragma unroll
        for (int mf=0; mf<2; mf++){
            const unsigned* bse = Ah + (mb+mf*16)*TSA + ks*8;
            const unsigned* bsl = Al + (mb+mf*16)*TSA + ks*8;
            ah[mf][0]=bse[ g   *TSA + c  ]; al[mf][0]=bsl[ g   *TSA + c  ];
            ah[mf][1]=bse[(g+8)*TSA + c  ]; al[mf][1]=bsl[(g+8)*TSA + c  ];
            ah[mf][2]=bse[ g   *TSA + c+4]; al[mf][2]=bsl[ g   *TSA + c+4];
            ah[mf][3]=bse[(g+8)*TSA + c+4]; al[mf][3]=bsl[(g+8)*TSA + c+4];
        }
        #pragma unroll
        for (int nf=0; nf<4; nf++){
            unsigned bh_[2], bl_[2];
            const unsigned* bse = Bh + (nb+nf*8+g)*TSA + ks*8;
            const unsigned* bsl = Bl + (nb+nf*8+g)*TSA + ks*8;
            bh_[0]=bse[c]; bh_[1]=bse[c+4];
            bl_[0]=bsl[c]; bl_[1]=bsl[c+4];
            #pragma unroll
            for (int mf=0; mf<2; mf++){
                mma_tf32(acc[mf][nf], ah[mf], bh_);
                mma_tf32(acc[mf][nf], ah[mf], bl_);
                mma_tf32(acc[mf][nf], al[mf], bh_);
            }
        }
    }
}

// ============================================================
// Kernel 1a: Q/K projections, EXACT fp32 scalar (R4 proven form).
// blockIdx.z in {0,1} selects (query,Wq,bq,gQ) / (key,Wk,bk,gK).
// Q/K feed the top-k threshold: their arithmetic must stay exact fp32.
// ============================================================
__global__ __launch_bounds__(256) void projqk_kernel(
    const float* __restrict__ Aq, const float* __restrict__ Ak,
    const float* __restrict__ Wq, const float* __restrict__ Wk,
    const float* __restrict__ bq, const float* __restrict__ bk,
    float* __restrict__ Oq, float* __restrict__ Ok)
{
    const float* A; const float* W; const float* bias; float* Out;
    if (blockIdx.z == 0) { A = Aq; W = Wq; bias = bq; Out = Oq; }
    else                 { A = Ak; W = Wk; bias = bk; Out = Ok; }

    const int BK = 16;
    __shared__ float As[BK][128];
    __shared__ float Bs[BK][128];
    int m0 = blockIdx.y * 128;
    int n0 = blockIdx.x * 128;
    int tid = threadIdx.x;
    float acc[8][8];
    #pragma unroll
    for (int i=0;i<8;i++)
        #pragma unroll
        for (int j=0;j<8;j++) acc[i][j]=0.f;

    for (int k0 = 0; k0 < Dn; k0 += BK) {
        #pragma unroll
        for (int i = 0; i < 2; i++) {
            int idx = tid + i*256;
            int r = idx >> 2;
            int c4 = idx & 3;
            float4 v = *(const float4*)(A + (size_t)(m0 + r)*Dn + k0 + c4*4);
            As[c4*4+0][r]=v.x; As[c4*4+1][r]=v.y; As[c4*4+2][r]=v.z; As[c4*4+3][r]=v.w;
        }
        #pragma unroll
        for (int i = 0; i < 2; i++) {
            int idx = tid + i*256;
            int r = idx >> 2;
            int c4 = idx & 3;
            float4 v = *(const float4*)(W + (size_t)(n0 + r)*Dn + k0 + c4*4);
            Bs[c4*4+0][r]=v.x; Bs[c4*4+1][r]=v.y; Bs[c4*4+2][r]=v.z; Bs[c4*4+3][r]=v.w;
        }
        __syncthreads();
        int tx = tid & 15, ty = tid >> 4;
        #pragma unroll
        for (int kk = 0; kk < BK; kk++) {
            float a[8], b[8];
            #pragma unroll
            for (int i=0;i<8;i++) a[i] = As[kk][ty*8+i];
            #pragma unroll
            for (int j=0;j<8;j++) b[j] = Bs[kk][tx*8+j];
            #pragma unroll
            for (int i=0;i<8;i++)
                #pragma unroll
                for (int j=0;j<8;j++) acc[i][j] += a[i]*b[j];
        }
        __syncthreads();
    }
    int tx = tid & 15, ty = tid >> 4;
    #pragma unroll
    for (int i=0;i<8;i++){
        int m = m0 + ty*8 + i;
        int b = m / Sn, s = m % Sn;
        #pragma unroll
        for (int j=0;j<8;j++){
            int n = n0 + tx*8 + j;
            int h = n >> 6, hd = n & 63;
            Out[(((size_t)(b*Hn + h))*Sn + s)*HDn + hd] = acc[i][j] + bias[n];
        }
    }
}

// ============================================================
// Kernel 1b: V projection via tf32x3 MMA (flip-safe: V never enters top-k).
// Block 128m x 64n, k streamed in 64-chunks.
// ============================================================
__global__ __launch_bounds__(256) void projv_mma_kernel(
    const float* __restrict__ A, const float* __restrict__ W,
    const float* __restrict__ bias, float* __restrict__ Out)
{
    extern __shared__ unsigned sm[];
    unsigned* Ah = sm;
    unsigned* Al = Ah + 128*TSA;
    unsigned* Bh = Al + 128*TSA;
    unsigned* Bl = Bh + 64*TSA;

    int m0 = blockIdx.y * 128;
    int n0 = blockIdx.x * 64;
    int tid = threadIdx.x;
    int lane = tid & 31, w = tid >> 5;
    int mb = (w >> 1) * 32, nb = (w & 1) * 32;
    int g = lane >> 2, c = lane & 3;

    float acc[2][4][4];
    #pragma unroll
    for (int mf=0;mf<2;mf++)
        #pragma unroll
        for (int nf=0;nf<4;nf++)
            #pragma unroll
            for (int e=0;e<4;e++) acc[mf][nf][e]=0.f;

    for (int k0 = 0; k0 < Dn; k0 += 64) {
        #pragma unroll
        for (int i = 0; i < 8; i++){
            int idx = tid + i*256;
            int r = idx >> 4, c4 = idx & 15;
            float4 v = *(const float4*)(A + (size_t)(m0+r)*Dn + k0 + c4*4);
            uint4 hi, lo; split4(v, hi, lo);
            *(uint4*)&Ah[r*TSA + c4*4] = hi;
            *(uint4*)&Al[r*TSA + c4*4] = lo;
        }
        #pragma unroll
        for (int i = 0; i < 4; i++){
            int idx = tid + i*256;
            int r = idx >> 4, c4 = idx & 15;
            float4 v = *(const float4*)(W + (size_t)(n0+r)*Dn + k0 + c4*4);
            uint4 hi, lo; split4(v, hi, lo);
            *(uint4*)&Bh[r*TSA + c4*4] = hi;
            *(uint4*)&Bl[r*TSA + c4*4] = lo;
        }
        __syncthreads();
        mma_chunk_rowB(acc, Ah, Al, Bh, Bl, mb, nb, g, c);
        __syncthreads();
    }

    #pragma unroll
    for (int mf=0; mf<2; mf++){
        #pragma unroll
        for (int nf=0; nf<4; nf++){
            int col = n0 + nb + nf*8 + 2*c;
            int h = col >> 6, hd = col & 63;
            float b0 = bias[col], b1 = bias[col+1];
            #pragma unroll
            for (int rr = 0; rr < 2; rr++){
                int row = m0 + mb + mf*16 + g + rr*8;
                int b = row / Sn, s = row % Sn;
                float2 v = make_float2(acc[mf][nf][2*rr] + b0, acc[mf][nf][2*rr+1] + b1);
                *(float2*)&Out[(((size_t)(b*Hn + h))*Sn + s)*HDn + hd] = v;
            }
        }
    }
}

// ============================================================
// Kernel 2: scores via tf32x3 MMA (R10 form; numerics == R9 passing kernel)
// ============================================================
__global__ __launch_bounds__(256) void scores_mma_kernel(float* __restrict__ attn)
{
    extern __shared__ unsigned sm[];
    unsigned* Ah = sm;
    unsigned* Al = Ah + 128*TSA;
    unsigned* Bh = Al + 128*TSA;
    unsigned* Bl = Bh + 64*TSA;

    int bh = blockIdx.z;
    int q0 = blockIdx.y * 128;
    int n0 = blockIdx.x * 64;
    const float* Qb = g_Q + (size_t)bh*Sn*HDn;
    const float* Kb = g_K + (size_t)bh*Sn*HDn;
    float* Cb = attn + (size_t)bh*Sn*Sn;
    int tid = threadIdx.x;
    int lane = tid & 31, w = tid >> 5;
    int mb = (w >> 1) * 32, nb = (w & 1) * 32;
    int g = lane >> 2, c = lane & 3;

    #pragma unroll
    for (int i = 0; i < 8; i++){
        int idx = tid + i*256;
        int r = idx >> 4, c4 = idx & 15;
        float4 v = *(const float4*)(Qb + (size_t)(q0+r)*HDn + c4*4);
        uint4 hi, lo; split4(v, hi, lo);
        *(uint4*)&Ah[r*TSA + c4*4] = hi;
        *(uint4*)&Al[r*TSA + c4*4] = lo;
    }
    #pragma unroll
    for (int i = 0; i < 4; i++){
        int idx = tid + i*256;
        int r = idx >> 4, c4 = idx & 15;
        float4 v = *(const float4*)(Kb + (size_t)(n0+r)*HDn + c4*4);
        uint4 hi, lo; split4(v, hi, lo);
        *(uint4*)&Bh[r*TSA + c4*4] = hi;
        *(uint4*)&Bl[r*TSA + c4*4] = lo;
    }
    __syncthreads();

    float acc[2][4][4];
    #pragma unroll
    for (int mf=0;mf<2;mf++)
        #pragma unroll
        for (int nf=0;nf<4;nf++)
            #pragma unroll
            for (int e=0;e<4;e++) acc[mf][nf][e]=0.f;

    mma_chunk_rowB(acc, Ah, Al, Bh, Bl, mb, nb, g, c);

    const float scale = 0.125f;
    #pragma unroll
    for (int mf=0; mf<2; mf++){
        #pragma unroll
        for (int nf=0; nf<4; nf++){
            int col = n0 + nb + nf*8 + 2*c;
            #pragma unroll
            for (int rr = 0; rr < 2; rr++){
                int row = q0 + mb + mf*16 + g + rr*8;
                float2 v = make_float2(acc[mf][nf][2*rr]*scale, acc[mf][nf][2*rr+1]*scale);
                *(float2*)(Cb + (size_t)row*Sn + col) = v;
            }
        }
    }
}

// ============================================================
// Kernel 3: per-WARP exact top-k + softmax (R8 proven)
// ============================================================
#define TKW 8
__global__ __launch_bounds__(256) void topk_softmax_kernel(float* __restrict__ attn)
{
    __shared__ unsigned hist[TKW][32*33];

    const int tid  = threadIdx.x;
    const int lane = tid & 31;
    const int w    = tid >> 5;
    const size_t row = (size_t)blockIdx.x * TKW + w;
    float* rowp = attn + row * (size_t)Sn;
    unsigned* H = hist[w];

    unsigned ku[64];
    #pragma unroll
    for (int j = 0; j < 16; j++) {
        float4 v = *(const float4*)(rowp + lane*4 + j*128);
        ku[j*4+0]=fkey(v.x); ku[j*4+1]=fkey(v.y); ku[j*4+2]=fkey(v.z); ku[j*4+3]=fkey(v.w);
    }
    unsigned kmax = 0u;
    #pragma unroll
    for (int e = 0; e < 64; e++) kmax = max(kmax, ku[e]);
    #pragma unroll
    for (int o=16;o>0;o>>=1) kmax = max(kmax, __shfl_xor_sync(0xffffffffu, kmax, o));
    float gmax = finv(kmax);

    unsigned prefix = 0u;
    int r = KSEL;
    #pragma unroll 1
    for (int p = 0; p < 6; p++) {
        const int shift = (p < 5) ? (26 - 6*p) : 0;
        const int nbit  = (p < 5) ? 6 : 2;
        const unsigned binmask = (1u << nbit) - 1u;
        const int sh2 = shift + nbit;
        const unsigned hm = (sh2 >= 32) ? 0u : (0xFFFFFFFFu << sh2);

        unsigned* reg = H + lane*33;
        #pragma unroll
        for (int i = 0; i < 33; i++) reg[i] = 0u;
        __syncwarp();
        #pragma unroll
        for (int e = 0; e < 64; e++) {
            unsigned u = ku[e];
            if ((u & hm) == prefix) {
                unsigned b = (u >> shift) & binmask;
                atomicAdd(&H[lane*33 + (b >> 1)], 1u << (16*(b & 1)));
            }
        }
        __syncwarp();
        unsigned acc = 0u;
        #pragma unroll
        for (int l = 0; l < 32; l++) acc += H[l*33 + lane];
        int cLo = (int)(acc & 0xFFFFu);
        int cHi = (int)(acc >> 16);
        int s   = cLo + cHi;
        int suf = s;
        #pragma unroll
        for (int o = 1; o < 32; o <<= 1) {
            int v = __shfl_down_sync(0xffffffffu, suf, o);
            if (lane + o < 32) suf += v;
        }
        int geL = suf;
        int geH = suf - cLo;
        int geN = suf - s;
        int found = -1, rnew = 0;
        if (geH >= r && geN < r) { found = 2*lane + 1; rnew = r - geN; }
        if (geL >= r && geH < r) { found = 2*lane;     rnew = r - geH; }
        unsigned ball = __ballot_sync(0xffffffffu, found >= 0);
        int src = __ffs(ball) - 1;
        unsigned bsel = __shfl_sync(0xffffffffu, (unsigned)found, src);
        r = __shfl_sync(0xffffffffu, rnew, src);
        prefix |= (bsel << shift);
        __syncwarp();
    }
    unsigned thr = prefix;

    float lsumf = 0.f;
    #pragma unroll
    for (int e = 0; e < 64; e++) {
        unsigned k = ku[e];
        float ex = 0.f;
        if (k >= thr) ex = __expf(finv(k) - gmax);
        ku[e] = __float_as_uint(ex);
        lsumf += ex;
    }
    #pragma unroll
    for (int o=16;o>0;o>>=1) lsumf += __shfl_xor_sync(0xffffffffu, lsumf, o);
    float inv = 1.f / lsumf;
    #pragma unroll
    for (int j = 0; j < 16; j++) {
        float4 v = make_float4(__uint_as_float(ku[j*4+0])*inv,
                               __uint_as_float(ku[j*4+1])*inv,
                               __uint_as_float(ku[j*4+2])*inv,
                               __uint_as_float(ku[j*4+3])*inv);
        *(float4*)(rowp + lane*4 + j*128) = v;
    }
}

// ============================================================
// Kernel 4: AV via tf32x3 MMA (R10 form; numerics == R9 passing kernel)
// ============================================================
__global__ __launch_bounds__(256) void av_mma_kernel(const float* __restrict__ attn)
{
    extern __shared__ unsigned sm[];
    unsigned* Ah = sm;
    unsigned* Al = Ah + 128*TSA;
    unsigned* Vh = Al + 128*TSA;
    unsigned* Vl = Vh + 64*TSV;

    int bh = blockIdx.y;
    int m0 = blockIdx.x * 128;
    const float* Ab = attn + (size_t)bh*Sn*Sn;
    const float* Vb = g_V + (size_t)bh*Sn*HDn;
    float* Cb = g_AV + (size_t)bh*Sn*HDn;
    int tid = threadIdx.x;
    int lane = tid & 31, w = tid >> 5;
    int mb = (w >> 1) * 32, nb = (w & 1) * 32;
    int g = lane >> 2, c = lane & 3;

    float acc[2][4][4];
    #pragma unroll
    for (int mf=0;mf<2;mf++)
        #pragma unroll
        for (int nf=0;nf<4;nf++)
            #pragma unroll
            for (int e=0;e<4;e++) acc[mf][nf][e]=0.f;

    for (int k0 = 0; k0 < Sn; k0 += 64) {
        #pragma unroll
        for (int i = 0; i < 8; i++){
            int idx = tid + i*256;
            int r = idx >> 4, c4 = idx & 15;
            float4 v = *(const float4*)(Ab + (size_t)(m0+r)*Sn + k0 + c4*4);
            uint4 hi, lo; split4(v, hi, lo);
            *(uint4*)&Ah[r*TSA + c4*4] = hi;
            *(uint4*)&Al[r*TSA + c4*4] = lo;
        }
        #pragma unroll
        for (int i = 0; i < 4; i++){
            int idx = tid + i*256;
            int r = idx >> 4, c4 = idx & 15;
            float4 v = *(const float4*)(Vb + (size_t)(k0+r)*HDn + c4*4);
            uint4 hi, lo; split4(v, hi, lo);
            *(uint4*)&Vh[r*TSV + c4*4] = hi;
            *(uint4*)&Vl[r*TSV + c4*4] = lo;
        }
        __syncthreads();

        #pragma unroll
        for (int ks = 0; ks < 8; ks++){
            unsigned ah[2][4], al[2][4];
            #pragma unroll
            for (int mf=0; mf<2; mf++){
                const unsigned* bse = Ah + (mb+mf*16)*TSA + ks*8;
                const unsigned* bsl = Al + (mb+mf*16)*TSA + ks*8;
                ah[mf][0]=bse[ g   *TSA + c  ]; al[mf][0]=bsl[ g   *TSA + c  ];
                ah[mf][1]=bse[(g+8)*TSA + c  ]; al[mf][1]=bsl[(g+8)*TSA + c  ];
                ah[mf][2]=bse[ g   *TSA + c+4]; al[mf][2]=bsl[ g   *TSA + c+4];
                ah[mf][3]=bse[(g+8)*TSA + c+4]; al[mf][3]=bsl[(g+8)*TSA + c+4];
            }
            #pragma unroll
            for (int nf=0; nf<4; nf++){
                int d = nb + nf*8 + g;
                unsigned bh_[2], bl_[2];
                bh_[0]=Vh[(ks*8 + c    )*TSV + d]; bl_[0]=Vl[(ks*8 + c    )*TSV + d];
                bh_[1]=Vh[(ks*8 + c + 4)*TSV + d]; bl_[1]=Vl[(ks*8 + c + 4)*TSV + d];
                #pragma unroll
                for (int mf=0; mf<2; mf++){
                    mma_tf32(acc[mf][nf], ah[mf], bh_);
                    mma_tf32(acc[mf][nf], ah[mf], bl_);
                    mma_tf32(acc[mf][nf], al[mf], bh_);
                }
            }
        }
        __syncthreads();
    }

    #pragma unroll
    for (int mf=0; mf<2; mf++){
        #pragma unroll
        for (int nf=0; nf<4; nf++){
            int col = nb + nf*8 + 2*c;
            #pragma unroll
            for (int rr = 0; rr < 2; rr++){
                int row = m0 + mb + mf*16 + g + rr*8;
                float2 v = make_float2(acc[mf][nf][2*rr], acc[mf][nf][2*rr+1]);
                *(float2*)(Cb + (size_t)row*HDn + col) = v;
            }
        }
    }
}

// ============================================================
// Kernel 5: out projection via tf32x3 MMA (flip-safe: after attn).
// out[m][n] = sum_k AVview[m][k] * Wo[n][k] + bo[n]
// Each 64-k chunk lies entirely in head h = k0/64.
// ============================================================
__global__ __launch_bounds__(256) void outproj_mma_kernel(
    const float* __restrict__ Wo, const float* __restrict__ bo,
    float* __restrict__ out)
{
    extern __shared__ unsigned sm[];
    unsigned* Ah = sm;
    unsigned* Al = Ah + 128*TSA;
    unsigned* Bh = Al + 128*TSA;
    unsigned* Bl = Bh + 64*TSA;

    int m0 = blockIdx.y * 128;
    int n0 = blockIdx.x * 64;
    int tid = threadIdx.x;
    int lane = tid & 31, w = tid >> 5;
    int mb = (w >> 1) * 32, nb = (w & 1) * 32;
    int g = lane >> 2, c = lane & 3;

    float acc[2][4][4];
    #pragma unroll
    for (int mf=0;mf<2;mf++)
        #pragma unroll
        for (int nf=0;nf<4;nf++)
            #pragma unroll
            for (int e=0;e<4;e++) acc[mf][nf][e]=0.f;

    for (int k0 = 0; k0 < Dn; k0 += 64) {
        int h = k0 >> 6;
        #pragma unroll
        for (int i = 0; i < 8; i++){
            int idx = tid + i*256;
            int r = idx >> 4, c4 = idx & 15;   // r: m row, c4*4: hd within head
            int m = m0 + r;
            int b = m / Sn, s = m % Sn;
            float4 v = *(const float4*)(g_AV + (((size_t)(b*Hn + h))*Sn + s)*HDn + c4*4);
            uint4 hi, lo; split4(v, hi, lo);
            *(uint4*)&Ah[r*TSA + c4*4] = hi;
            *(uint4*)&Al[r*TSA + c4*4] = lo;
        }
        #pragma unroll
        for (int i = 0; i < 4; i++){
            int idx = tid + i*256;
            int r = idx >> 4, c4 = idx & 15;
            float4 v = *(const float4*)(Wo + (size_t)(n0+r)*Dn + k0 + c4*4);
            uint4 hi, lo; split4(v, hi, lo);
            *(uint4*)&Bh[r*TSA + c4*4] = hi;
            *(uint4*)&Bl[r*TSA + c4*4] = lo;
        }
        __syncthreads();
        mma_chunk_rowB(acc, Ah, Al, Bh, Bl, mb, nb, g, c);
        __syncthreads();
    }

    #pragma unroll
    for (int mf=0; mf<2; mf++){
        #pragma unroll
        for (int nf=0; nf<4; nf++){
            int col = n0 + nb + nf*8 + 2*c;
            float b0 = bo[col], b1 = bo[col+1];
            #pragma unroll
            for (int rr = 0; rr < 2; rr++){
                int row = m0 + mb + mf*16 + g + rr*8;
                float2 v = make_float2(acc[mf][nf][2*rr] + b0, acc[mf][nf][2*rr+1] + b1);
                *(float2*)(out + (size_t)row*Dn + col) = v;
            }
        }
    }
}

// ============================================================
extern "C" void kernel_launch(void* const* d_in, const int* in_sizes, int n_in,
                              void* d_out, int out_size)
{
    const float* query = (const float*)d_in[0];
    const float* key   = (const float*)d_in[1];
    const float* value = (const float*)d_in[2];
    const float* Wq = (const float*)d_in[3];
    const float* bq = (const float*)d_in[4];
    const float* Wk = (const float*)d_in[5];
    const float* bk = (const float*)d_in[6];
    const float* Wv = (const float*)d_in[7];
    const float* bv = (const float*)d_in[8];
    const float* Wo = (const float*)d_in[9];
    const float* bo = (const float*)d_in[10];

    float* out  = (float*)d_out;
    float* attn = out + (size_t)Bn * Sn * Dn;

    float* gQ;  cudaGetSymbolAddress((void**)&gQ,  g_Q);
    float* gK;  cudaGetSymbolAddress((void**)&gK,  g_K);
    float* gV;  cudaGetSymbolAddress((void**)&gV,  g_V);

    const int gemmSmem = (2*128*TSA + 2*64*TSA) * 4;       // 104448 B
    const int avSmem   = (2*128*TSA + 2*64*TSV) * 4;       // 106496 B
    cudaFuncSetAttribute(projv_mma_kernel,
        cudaFuncAttributeMaxDynamicSharedMemorySize, gemmSmem);
    cudaFuncSetAttribute(scores_mma_kernel,
        cudaFuncAttributeMaxDynamicSharedMemorySize, gemmSmem);
    cudaFuncSetAttribute(av_mma_kernel,
        cudaFuncAttributeMaxDynamicSharedMemorySize, avSmem);
    cudaFuncSetAttribute(outproj_mma_kernel,
        cudaFuncAttributeMaxDynamicSharedMemorySize, gemmSmem);

    dim3 projqkGrid(Dn/128, Mn/128, 2);         // (8, 32, 2) exact fp32
    projqk_kernel<<<projqkGrid, 256>>>(query, key, Wq, Wk, bq, bk, gQ, gK);

    dim3 projvGrid(Dn/64, Mn/128);              // (16, 32) tf32x3
    projv_mma_kernel<<<projvGrid, 256, gemmSmem>>>(value, Wv, bv, gV);

    dim3 scoreGrid(Sn/64, Sn/128, BHn);         // (32, 16, 32)
    scores_mma_kernel<<<scoreGrid, 256, gemmSmem>>>(attn);

    topk_softmax_kernel<<<BHn * Sn / TKW, 256>>>(attn);

    dim3 avGrid(Sn/128, BHn);                   // (16, 32)
    av_mma_kernel<<<avGrid, 256, avSmem>>>(attn);

    dim3 outGrid(Dn/64, Mn/128);                // (16, 32)
    outproj_mma_kernel<<<outGrid, 256, gemmSmem>>>(Wo, bo, out);
}

// round 13
// speedup vs baseline: 3.0406x; 1.1114x over previous
#include <cuda_runtime.h>
#include <cuda_bf16.h>
#include <cstdint>

#define Bn 2
#define Sn 2048
#define Dn 1024
#define Hn 16
#define HDn 64
#define BHn (Bn*Hn)
#define Mn (Bn*Sn)       // 4096
#define KSEL 1024        // top-k count

// ---- scratch (static device allocations; no cudaMalloc allowed) ----
__device__ float g_Q[Bn*Hn*Sn*HDn];   // (b,h,s,hd)
__device__ float g_K[Bn*Hn*Sn*HDn];
__device__ float g_V[Bn*Hn*Sn*HDn];
__device__ float g_AV[Bn*Hn*Sn*HDn];

// order-preserving float->uint key
__device__ __forceinline__ unsigned fkey(float f){
    unsigned uf = __float_as_uint(f);
    return (uf & 0x80000000u) ? ~uf : (uf | 0x80000000u);
}
__device__ __forceinline__ float finv(unsigned k){
    return __uint_as_float((k & 0x80000000u) ? (k & 0x7FFFFFFFu) : ~k);
}

// ---- tf32 helpers (scores only) ----
__device__ __forceinline__ void tf32split(float x, unsigned &hi, unsigned &lo){
    unsigned h; asm("cvt.rna.tf32.f32 %0, %1;" : "=r"(h) : "f"(x));
    float hf = __uint_as_float(h);
    asm("cvt.rna.tf32.f32 %0, %1;" : "=r"(lo) : "f"(x - hf));
    hi = h;
}
__device__ __forceinline__ void split4(float4 v, uint4 &hi, uint4 &lo){
    tf32split(v.x, hi.x, lo.x);
    tf32split(v.y, hi.y, lo.y);
    tf32split(v.z, hi.z, lo.z);
    tf32split(v.w, hi.w, lo.w);
}
__device__ __forceinline__ void mma_tf32(float* c, const unsigned* a, const unsigned* b){
    asm volatile("mma.sync.aligned.m16n8k8.row.col.f32.tf32.tf32.f32 "
        "{%0,%1,%2,%3}, {%4,%5,%6,%7}, {%8,%9}, {%0,%1,%2,%3};"
        : "+f"(c[0]), "+f"(c[1]), "+f"(c[2]), "+f"(c[3])
        : "r"(a[0]), "r"(a[1]), "r"(a[2]), "r"(a[3]), "r"(b[0]), "r"(b[1]));
}

// ---- bf16x3 helpers (linear-path GEMMs: vproj/av/outproj) ----
// pack two consecutive-k elements into one .b32 (low = even k), hi/lo split
__device__ __forceinline__ void bf16x2split(float x, float y, unsigned &hi, unsigned &lo){
    __nv_bfloat16 xh = __float2bfloat16_rn(x);
    __nv_bfloat16 yh = __float2bfloat16_rn(y);
    float xr = x - __bfloat162float(xh);
    float yr = y - __bfloat162float(yh);
    __nv_bfloat16 xl = __float2bfloat16_rn(xr);
    __nv_bfloat16 yl = __float2bfloat16_rn(yr);
    hi = (unsigned)__bfloat16_as_ushort(xh) | ((unsigned)__bfloat16_as_ushort(yh) << 16);
    lo = (unsigned)__bfloat16_as_ushort(xl) | ((unsigned)__bfloat16_as_ushort(yl) << 16);
}
__device__ __forceinline__ void mma_bf16(float* c, const unsigned* a, const unsigned* b){
    asm volatile("mma.sync.aligned.m16n8k16.row.col.f32.bf16.bf16.f32 "
        "{%0,%1,%2,%3}, {%4,%5,%6,%7}, {%8,%9}, {%0,%1,%2,%3};"
        : "+f"(c[0]), "+f"(c[1]), "+f"(c[2]), "+f"(c[3])
        : "r"(a[0]), "r"(a[1]), "r"(a[2]), "r"(a[3]), "r"(b[0]), "r"(b[1]));
}

// tile strides (u32 words)
#define TSA 68   // tf32 64-wide row tiles: (g*4+c)%32 distinct -> conflict-free
#define TS3 36   // bf16 32-word row tiles: (4g+c)%32 distinct -> conflict-free
#define TSV 72   // bf16 av V pair-row tiles: (8c+g)%32 distinct -> conflict-free

// tf32x3 warp micro: 32m x 32n, one 64-k chunk (scores)
__device__ __forceinline__ void mma_chunk_rowB(
    float acc[2][4][4], const unsigned* Ah, const unsigned* Al,
    const unsigned* Bh, const unsigned* Bl, int mb, int nb, int g, int c)
{
    #pragma unroll
    for (int ks = 0; ks < 8; ks++){
        unsigned ah[2][4], al[2][4];
        #pragma unroll
        for (int mf=0; mf<2; mf++){
            const unsigned* bse = Ah + (mb+mf*16)*TSA + ks*8;
            const unsigned* bsl = Al + (mb+mf*16)*TSA + ks*8;
            ah[mf][0]=bse[ g   *TSA + c  ]; al[mf][0]=bsl[ g   *TSA + c  ];
            ah[mf][1]=bse[(g+8)*TSA + c  ]; al[mf][1]=bsl[(g+8)*TSA + c  ];
            ah[mf][2]=bse[ g   *TSA + c+4]; al[mf][2]=bsl[ g   *TSA + c+4];
            ah[mf][3]=bse[(g+8)*TSA + c+4]; al[mf][3]=bsl[(g+8)*TSA + c+4];
        }
        #pragma unroll
        for (int nf=0; nf<4; nf++){
            unsigned bh_[2], bl_[2];
            const unsigned* bse = Bh + (nb+nf*8+g)*TSA + ks*8;
            const unsigned* bsl = Bl + (nb+nf*8+g)*TSA + ks*8;
            bh_[0]=bse[c]; bh_[1]=bse[c+4];
            bl_[0]=bsl[c]; bl_[1]=bsl[c+4];
            #pragma unroll
            for (int mf=0; mf<2; mf++){
                mma_tf32(acc[mf][nf], ah[mf], bh_);
                mma_tf32(acc[mf][nf], ah[mf], bl_);
                mma_tf32(acc[mf][nf], al[mf], bh_);
            }
        }
    }
}

// bf16x3 warp micro: 32m x 32n, one 64-k chunk (word tiles, rowB pattern)
__device__ __forceinline__ void mma_chunk_rowB_bf16(
    float acc[2][4][4], const unsigned* Ah, const unsigned* Al,
    const unsigned* Bh, const unsigned* Bl, int mb, int nb, int g, int c)
{
    #pragma unroll
    for (int ks = 0; ks < 4; ks++){               // 4 k-steps of 16
        unsigned ah[2][4], al[2][4];
        #pragma unroll
        for (int mf=0; mf<2; mf++){
            const unsigned* ph = Ah + (mb+mf*16)*TS3 + ks*8;
            const unsigned* pl = Al + (mb+mf*16)*TS3 + ks*8;
            ah[mf][0]=ph[ g   *TS3 + c  ]; al[mf][0]=pl[ g   *TS3 + c  ];
            ah[mf][1]=ph[(g+8)*TS3 + c  ]; al[mf][1]=pl[(g+8)*TS3 + c  ];
            ah[mf][2]=ph[ g   *TS3 + c+4]; al[mf][2]=pl[ g   *TS3 + c+4];
            ah[mf][3]=ph[(g+8)*TS3 + c+4]; al[mf][3]=pl[(g+8)*TS3 + c+4];
        }
        #pragma unroll
        for (int nf=0; nf<4; nf++){
            const unsigned* ph = Bh + (nb+nf*8+g)*TS3 + ks*8;
            const unsigned* pl = Bl + (nb+nf*8+g)*TS3 + ks*8;
            unsigned bh_[2] = { ph[c], ph[c+4] };
            unsigned bl_[2] = { pl[c], pl[c+4] };
            #pragma unroll
            for (int mf=0; mf<2; mf++){
                mma_bf16(acc[mf][nf], ah[mf], bh_);
                mma_bf16(acc[mf][nf], ah[mf], bl_);
                mma_bf16(acc[mf][nf], al[mf], bh_);
            }
        }
    }
}

// ============================================================
// Kernel 1a: Q/K projections, EXACT fp32 scalar (R11 proven — flip-critical)
// ============================================================
__global__ __launch_bounds__(256) void projqk_kernel(
    const float* __restrict__ Aq, const float* __restrict__ Ak,
    const float* __restrict__ Wq, const float* __restrict__ Wk,
    const float* __restrict__ bq, const float* __restrict__ bk,
    float* __restrict__ Oq, float* __restrict__ Ok)
{
    const float* A; const float* W; const float* bias; float* Out;
    if (blockIdx.z == 0) { A = Aq; W = Wq; bias = bq; Out = Oq; }
    else                 { A = Ak; W = Wk; bias = bk; Out = Ok; }

    const int BK = 16;
    __shared__ float As[BK][128];
    __shared__ float Bs[BK][128];
    int m0 = blockIdx.y * 128;
    int n0 = blockIdx.x * 128;
    int tid = threadIdx.x;
    float acc[8][8];
    #pragma unroll
    for (int i=0;i<8;i++)
        #pragma unroll
        for (int j=0;j<8;j++) acc[i][j]=0.f;

    for (int k0 = 0; k0 < Dn; k0 += BK) {
        #pragma unroll
        for (int i = 0; i < 2; i++) {
            int idx = tid + i*256;
            int r = idx >> 2;
            int c4 = idx & 3;
            float4 v = *(const float4*)(A + (size_t)(m0 + r)*Dn + k0 + c4*4);
            As[c4*4+0][r]=v.x; As[c4*4+1][r]=v.y; As[c4*4+2][r]=v.z; As[c4*4+3][r]=v.w;
        }
        #pragma unroll
        for (int i = 0; i < 2; i++) {
            int idx = tid + i*256;
            int r = idx >> 2;
            int c4 = idx & 3;
            float4 v = *(const float4*)(W + (size_t)(n0 + r)*Dn + k0 + c4*4);
            Bs[c4*4+0][r]=v.x; Bs[c4*4+1][r]=v.y; Bs[c4*4+2][r]=v.z; Bs[c4*4+3][r]=v.w;
        }
        __syncthreads();
        int tx = tid & 15, ty = tid >> 4;
        #pragma unroll
        for (int kk = 0; kk < BK; kk++) {
            float a[8], b[8];
            #pragma unroll
            for (int i=0;i<8;i++) a[i] = As[kk][ty*8+i];
            #pragma unroll
            for (int j=0;j<8;j++) b[j] = Bs[kk][tx*8+j];
            #pragma unroll
            for (int i=0;i<8;i++)
                #pragma unroll
                for (int j=0;j<8;j++) acc[i][j] += a[i]*b[j];
        }
        __syncthreads();
    }
    int tx = tid & 15, ty = tid >> 4;
    #pragma unroll
    for (int i=0;i<8;i++){
        int m = m0 + ty*8 + i;
        int b = m / Sn, s = m % Sn;
        #pragma unroll
        for (int j=0;j<8;j++){
            int n = n0 + tx*8 + j;
            int h = n >> 6, hd = n & 63;
            Out[(((size_t)(b*Hn + h))*Sn + s)*HDn + hd] = acc[i][j] + bias[n];
        }
    }
}

// ============================================================
// Kernel 1b: V projection via bf16x3 MMA (linear path — flip-safe)
// Block 128m x 64n, k streamed in 64-chunks.
// ============================================================
__global__ __launch_bounds__(256) void projv_bf16_kernel(
    const float* __restrict__ A, const float* __restrict__ W,
    const float* __restrict__ bias, float* __restrict__ Out)
{
    extern __shared__ unsigned sm[];
    unsigned* Ah = sm;                 // 128*TS3
    unsigned* Al = Ah + 128*TS3;
    unsigned* Bh = Al + 128*TS3;       // 64*TS3
    unsigned* Bl = Bh + 64*TS3;

    int m0 = blockIdx.y * 128;
    int n0 = blockIdx.x * 64;
    int tid = threadIdx.x;
    int lane = tid & 31, w = tid >> 5;
    int mb = (w >> 1) * 32, nb = (w & 1) * 32;
    int g = lane >> 2, c = lane & 3;

    float acc[2][4][4];
    #pragma unroll
    for (int mf=0;mf<2;mf++)
        #pragma unroll
        for (int nf=0;nf<4;nf++)
            #pragma unroll
            for (int e=0;e<4;e++) acc[mf][nf][e]=0.f;

    for (int k0 = 0; k0 < Dn; k0 += 64) {
        #pragma unroll
        for (int i = 0; i < 8; i++){
            int idx = tid + i*256;          // 0..2047
            int r = idx >> 4, c4 = idx & 15;
            float4 v = *(const float4*)(A + (size_t)(m0+r)*Dn + k0 + c4*4);
            unsigned h0,l0,h1,l1;
            bf16x2split(v.x, v.y, h0, l0);
            bf16x2split(v.z, v.w, h1, l1);
            *(uint2*)&Ah[r*TS3 + c4*2] = make_uint2(h0, h1);
            *(uint2*)&Al[r*TS3 + c4*2] = make_uint2(l0, l1);
        }
        #pragma unroll
        for (int i = 0; i < 4; i++){
            int idx = tid + i*256;          // 0..1023
            int r = idx >> 4, c4 = idx & 15;
            float4 v = *(const float4*)(W + (size_t)(n0+r)*Dn + k0 + c4*4);
            unsigned h0,l0,h1,l1;
            bf16x2split(v.x, v.y, h0, l0);
            bf16x2split(v.z, v.w, h1, l1);
            *(uint2*)&Bh[r*TS3 + c4*2] = make_uint2(h0, h1);
            *(uint2*)&Bl[r*TS3 + c4*2] = make_uint2(l0, l1);
        }
        __syncthreads();
        mma_chunk_rowB_bf16(acc, Ah, Al, Bh, Bl, mb, nb, g, c);
        __syncthreads();
    }

    #pragma unroll
    for (int mf=0; mf<2; mf++){
        #pragma unroll
        for (int nf=0; nf<4; nf++){
            int col = n0 + nb + nf*8 + 2*c;
            int h = col >> 6, hd = col & 63;
            float b0 = bias[col], b1 = bias[col+1];
            #pragma unroll
            for (int rr = 0; rr < 2; rr++){
                int row = m0 + mb + mf*16 + g + rr*8;
                int b = row / Sn, s = row % Sn;
                float2 v = make_float2(acc[mf][nf][2*rr] + b0, acc[mf][nf][2*rr+1] + b1);
                *(float2*)&Out[(((size_t)(b*Hn + h))*Sn + s)*HDn + hd] = v;
            }
        }
    }
}

// ============================================================
// Kernel 2: scores via tf32x3 MMA (R11 proven — flip-sensitive, unchanged)
// ============================================================
__global__ __launch_bounds__(256) void scores_mma_kernel(float* __restrict__ attn)
{
    extern __shared__ unsigned sm[];
    unsigned* Ah = sm;
    unsigned* Al = Ah + 128*TSA;
    unsigned* Bh = Al + 128*TSA;
    unsigned* Bl = Bh + 64*TSA;

    int bh = blockIdx.z;
    int q0 = blockIdx.y * 128;
    int n0 = blockIdx.x * 64;
    const float* Qb = g_Q + (size_t)bh*Sn*HDn;
    const float* Kb = g_K + (size_t)bh*Sn*HDn;
    float* Cb = attn + (size_t)bh*Sn*Sn;
    int tid = threadIdx.x;
    int lane = tid & 31, w = tid >> 5;
    int mb = (w >> 1) * 32, nb = (w & 1) * 32;
    int g = lane >> 2, c = lane & 3;

    #pragma unroll
    for (int i = 0; i < 8; i++){
        int idx = tid + i*256;
        int r = idx >> 4, c4 = idx & 15;
        float4 v = *(const float4*)(Qb + (size_t)(q0+r)*HDn + c4*4);
        uint4 hi, lo; split4(v, hi, lo);
        *(uint4*)&Ah[r*TSA + c4*4] = hi;
        *(uint4*)&Al[r*TSA + c4*4] = lo;
    }
    #pragma unroll
    for (int i = 0; i < 4; i++){
        int idx = tid + i*256;
        int r = idx >> 4, c4 = idx & 15;
        float4 v = *(const float4*)(Kb + (size_t)(n0+r)*HDn + c4*4);
        uint4 hi, lo; split4(v, hi, lo);
        *(uint4*)&Bh[r*TSA + c4*4] = hi;
        *(uint4*)&Bl[r*TSA + c4*4] = lo;
    }
    __syncthreads();

    float acc[2][4][4];
    #pragma unroll
    for (int mf=0;mf<2;mf++)
        #pragma unroll
        for (int nf=0;nf<4;nf++)
            #pragma unroll
            for (int e=0;e<4;e++) acc[mf][nf][e]=0.f;

    mma_chunk_rowB(acc, Ah, Al, Bh, Bl, mb, nb, g, c);

    const float scale = 0.125f;
    #pragma unroll
    for (int mf=0; mf<2; mf++){
        #pragma unroll
        for (int nf=0; nf<4; nf++){
            int col = n0 + nb + nf*8 + 2*c;
            #pragma unroll
            for (int rr = 0; rr < 2; rr++){
                int row = q0 + mb + mf*16 + g + rr*8;
                float2 v = make_float2(acc[mf][nf][2*rr]*scale, acc[mf][nf][2*rr+1]*scale);
                *(float2*)(Cb + (size_t)row*Sn + col) = v;
            }
        }
    }
}

// ============================================================
// Kernel 3: per-WARP exact top-k + softmax (R8 proven)
// ============================================================
#define TKW 8
__global__ __launch_bounds__(256) void topk_softmax_kernel(float* __restrict__ attn)
{
    __shared__ unsigned hist[TKW][32*33];

    const int tid  = threadIdx.x;
    const int lane = tid & 31;
    const int w    = tid >> 5;
    const size_t row = (size_t)blockIdx.x * TKW + w;
    float* rowp = attn + row * (size_t)Sn;
    unsigned* H = hist[w];

    unsigned ku[64];
    #pragma unroll
    for (int j = 0; j < 16; j++) {
        float4 v = *(const float4*)(rowp + lane*4 + j*128);
        ku[j*4+0]=fkey(v.x); ku[j*4+1]=fkey(v.y); ku[j*4+2]=fkey(v.z); ku[j*4+3]=fkey(v.w);
    }
    unsigned kmax = 0u;
    #pragma unroll
    for (int e = 0; e < 64; e++) kmax = max(kmax, ku[e]);
    #pragma unroll
    for (int o=16;o>0;o>>=1) kmax = max(kmax, __shfl_xor_sync(0xffffffffu, kmax, o));
    float gmax = finv(kmax);

    unsigned prefix = 0u;
    int r = KSEL;
    #pragma unroll 1
    for (int p = 0; p < 6; p++) {
        const int shift = (p < 5) ? (26 - 6*p) : 0;
        const int nbit  = (p < 5) ? 6 : 2;
        const unsigned binmask = (1u << nbit) - 1u;
        const int sh2 = shift + nbit;
        const unsigned hm = (sh2 >= 32) ? 0u : (0xFFFFFFFFu << sh2);

        unsigned* reg = H + lane*33;
        #pragma unroll
        for (int i = 0; i < 33; i++) reg[i] = 0u;
        __syncwarp();
        #pragma unroll
        for (int e = 0; e < 64; e++) {
            unsigned u = ku[e];
            if ((u & hm) == prefix) {
                unsigned b = (u >> shift) & binmask;
                atomicAdd(&H[lane*33 + (b >> 1)], 1u << (16*(b & 1)));
            }
        }
        __syncwarp();
        unsigned acc = 0u;
        #pragma unroll
        for (int l = 0; l < 32; l++) acc += H[l*33 + lane];
        int cLo = (int)(acc & 0xFFFFu);
        int cHi = (int)(acc >> 16);
        int s   = cLo + cHi;
        int suf = s;
        #pragma unroll
        for (int o = 1; o < 32; o <<= 1) {
            int v = __shfl_down_sync(0xffffffffu, suf, o);
            if (lane + o < 32) suf += v;
        }
        int geL = suf;
        int geH = suf - cLo;
        int geN = suf - s;
        int found = -1, rnew = 0;
        if (geH >= r && geN < r) { found = 2*lane + 1; rnew = r - geN; }
        if (geL >= r && geH < r) { found = 2*lane;     rnew = r - geH; }
        unsigned ball = __ballot_sync(0xffffffffu, found >= 0);
        int src = __ffs(ball) - 1;
        unsigned bsel = __shfl_sync(0xffffffffu, (unsigned)found, src);
        r = __shfl_sync(0xffffffffu, rnew, src);
        prefix |= (bsel << shift);
        __syncwarp();
    }
    unsigned thr = prefix;

    float lsumf = 0.f;
    #pragma unroll
    for (int e = 0; e < 64; e++) {
        unsigned k = ku[e];
        float ex = 0.f;
        if (k >= thr) ex = __expf(finv(k) - gmax);
        ku[e] = __float_as_uint(ex);
        lsumf += ex;
    }
    #pragma unroll
    for (int o=16;o>0;o>>=1) lsumf += __shfl_xor_sync(0xffffffffu, lsumf, o);
    float inv = 1.f / lsumf;
    #pragma unroll
    for (int j = 0; j < 16; j++) {
        float4 v = make_float4(__uint_as_float(ku[j*4+0])*inv,
                               __uint_as_float(ku[j*4+1])*inv,
                               __uint_as_float(ku[j*4+2])*inv,
                               __uint_as_float(ku[j*4+3])*inv);
        *(float4*)(rowp + lane*4 + j*128) = v;
    }
}

// ============================================================
// Kernel 4: AV via bf16x3 MMA (linear path — flip-safe).
// Block 128q x 64d, k streamed in 64-chunks. V word tiles pair k-rows.
// ============================================================
__global__ __launch_bounds__(256) void av_bf16_kernel(const float* __restrict__ attn)
{
    extern __shared__ unsigned sm[];
    unsigned* Ah = sm;                 // 128*TS3
    unsigned* Al = Ah + 128*TS3;
    unsigned* Vh = Al + 128*TS3;       // 32*TSV (pair-rows)
    unsigned* Vl = Vh + 32*TSV;

    int bh = blockIdx.y;
    int m0 = blockIdx.x * 128;
    const float* Ab = attn + (size_t)bh*Sn*Sn;
    const float* Vb = g_V + (size_t)bh*Sn*HDn;
    float* Cb = g_AV + (size_t)bh*Sn*HDn;
    int tid = threadIdx.x;
    int lane = tid & 31, w = tid >> 5;
    int mb = (w >> 1) * 32, nb = (w & 1) * 32;
    int g = lane >> 2, c = lane & 3;

    float acc[2][4][4];
    #pragma unroll
    for (int mf=0;mf<2;mf++)
        #pragma unroll
        for (int nf=0;nf<4;nf++)
            #pragma unroll
            for (int e=0;e<4;e++) acc[mf][nf][e]=0.f;

    for (int k0 = 0; k0 < Sn; k0 += 64) {
        // A (attn) tile: 128 x 64 -> word-packed pairs along k
        #pragma unroll
        for (int i = 0; i < 8; i++){
            int idx = tid + i*256;
            int r = idx >> 4, c4 = idx & 15;
            float4 v = *(const float4*)(Ab + (size_t)(m0+r)*Sn + k0 + c4*4);
            unsigned h0,l0,h1,l1;
            bf16x2split(v.x, v.y, h0, l0);
            bf16x2split(v.z, v.w, h1, l1);
            *(uint2*)&Ah[r*TS3 + c4*2] = make_uint2(h0, h1);
            *(uint2*)&Al[r*TS3 + c4*2] = make_uint2(l0, l1);
        }
        // V tile: 64 k-rows x 64 d -> 32 pair-rows, word = (V[2pr][d], V[2pr+1][d])
        #pragma unroll
        for (int i = 0; i < 2; i++){
            int idx = tid + i*256;          // 0..511
            int pr = idx >> 4, c4 = idx & 15;
            int d = c4 * 4;
            float4 v0 = *(const float4*)(Vb + (size_t)(k0 + 2*pr    )*HDn + d);
            float4 v1 = *(const float4*)(Vb + (size_t)(k0 + 2*pr + 1)*HDn + d);
            unsigned h, l;
            bf16x2split(v0.x, v1.x, h, l); Vh[pr*TSV + d + 0] = h; Vl[pr*TSV + d + 0] = l;
            bf16x2split(v0.y, v1.y, h, l); Vh[pr*TSV + d + 1] = h; Vl[pr*TSV + d + 1] = l;
            bf16x2split(v0.z, v1.z, h, l); Vh[pr*TSV + d + 2] = h; Vl[pr*TSV + d + 2] = l;
            bf16x2split(v0.w, v1.w, h, l); Vh[pr*TSV + d + 3] = h; Vl[pr*TSV + d + 3] = l;
        }
        __syncthreads();

        #pragma unroll
        for (int ks = 0; ks < 4; ks++){
            unsigned ah[2][4], al[2][4];
            #pragma unroll
            for (int mf=0; mf<2; mf++){
                const unsigned* ph = Ah + (mb+mf*16)*TS3 + ks*8;
                const unsigned* pl = Al + (mb+mf*16)*TS3 + ks*8;
                ah[mf][0]=ph[ g   *TS3 + c  ]; al[mf][0]=pl[ g   *TS3 + c  ];
                ah[mf][1]=ph[(g+8)*TS3 + c  ]; al[mf][1]=pl[(g+8)*TS3 + c  ];
                ah[mf][2]=ph[ g   *TS3 + c+4]; al[mf][2]=pl[ g   *TS3 + c+4];
                ah[mf][3]=ph[(g+8)*TS3 + c+4]; al[mf][3]=pl[(g+8)*TS3 + c+4];
            }
            #pragma unroll
            for (int nf=0; nf<4; nf++){
                int d = nb + nf*8 + g;
                unsigned bh_[2], bl_[2];
                bh_[0]=Vh[(ks*8 + c    )*TSV + d]; bl_[0]=Vl[(ks*8 + c    )*TSV + d];
                bh_[1]=Vh[(ks*8 + c + 4)*TSV + d]; bl_[1]=Vl[(ks*8 + c + 4)*TSV + d];
                #pragma unroll
                for (int mf=0; mf<2; mf++){
                    mma_bf16(acc[mf][nf], ah[mf], bh_);
                    mma_bf16(acc[mf][nf], ah[mf], bl_);
                    mma_bf16(acc[mf][nf], al[mf], bh_);
                }
            }
        }
        __syncthreads();
    }

    #pragma unroll
    for (int mf=0; mf<2; mf++){
        #pragma unroll
        for (int nf=0; nf<4; nf++){
            int col = nb + nf*8 + 2*c;
            #pragma unroll
            for (int rr = 0; rr < 2; rr++){
                int row = m0 + mb + mf*16 + g + rr*8;
                float2 v = make_float2(acc[mf][nf][2*rr], acc[mf][nf][2*rr+1]);
                *(float2*)(Cb + (size_t)row*HDn + col) = v;
            }
        }
    }
}

// ============================================================
// Kernel 5: out projection via bf16x3 MMA (linear path — flip-safe)
// ============================================================
__global__ __launch_bounds__(256) void outproj_bf16_kernel(
    const float* __restrict__ Wo, const float* __restrict__ bo,
    float* __restrict__ out)
{
    extern __shared__ unsigned sm[];
    unsigned* Ah = sm;
    unsigned* Al = Ah + 128*TS3;
    unsigned* Bh = Al + 128*TS3;
    unsigned* Bl = Bh + 64*TS3;

    int m0 = blockIdx.y * 128;
    int n0 = blockIdx.x * 64;
    int tid = threadIdx.x;
    int lane = tid & 31, w = tid >> 5;
    int mb = (w >> 1) * 32, nb = (w & 1) * 32;
    int g = lane >> 2, c = lane & 3;

    float acc[2][4][4];
    #pragma unroll
    for (int mf=0;mf<2;mf++)
        #pragma unroll
        for (int nf=0;nf<4;nf++)
            #pragma unroll
            for (int e=0;e<4;e++) acc[mf][nf][e]=0.f;

    for (int k0 = 0; k0 < Dn; k0 += 64) {
        int h = k0 >> 6;
        #pragma unroll
        for (int i = 0; i < 8; i++){
            int idx = tid + i*256;
            int r = idx >> 4, c4 = idx & 15;
            int m = m0 + r;
            int b = m / Sn, s = m % Sn;
            float4 v = *(const float4*)(g_AV + (((size_t)(b*Hn + h))*Sn + s)*HDn + c4*4);
            unsigned h0,l0,h1,l1;
            bf16x2split(v.x, v.y, h0, l0);
            bf16x2split(v.z, v.w, h1, l1);
            *(uint2*)&Ah[r*TS3 + c4*2] = make_uint2(h0, h1);
            *(uint2*)&Al[r*TS3 + c4*2] = make_uint2(l0, l1);
        }
        #pragma unroll
        for (int i = 0; i < 4; i++){
            int idx = tid + i*256;
            int r = idx >> 4, c4 = idx & 15;
            float4 v = *(const float4*)(Wo + (size_t)(n0+r)*Dn + k0 + c4*4);
            unsigned h0,l0,h1,l1;
            bf16x2split(v.x, v.y, h0, l0);
            bf16x2split(v.z, v.w, h1, l1);
            *(uint2*)&Bh[r*TS3 + c4*2] = make_uint2(h0, h1);
            *(uint2*)&Bl[r*TS3 + c4*2] = make_uint2(l0, l1);
        }
        __syncthreads();
        mma_chunk_rowB_bf16(acc, Ah, Al, Bh, Bl, mb, nb, g, c);
        __syncthreads();
    }

    #pragma unroll
    for (int mf=0; mf<2; mf++){
        #pragma unroll
        for (int nf=0; nf<4; nf++){
            int col = n0 + nb + nf*8 + 2*c;
            float b0 = bo[col], b1 = bo[col+1];
            #pragma unroll
            for (int rr = 0; rr < 2; rr++){
                int row = m0 + mb + mf*16 + g + rr*8;
                float2 v = make_float2(acc[mf][nf][2*rr] + b0, acc[mf][nf][2*rr+1] + b1);
                *(float2*)(out + (size_t)row*Dn + col) = v;
            }
        }
    }
}

// ============================================================
extern "C" void kernel_launch(void* const* d_in, const int* in_sizes, int n_in,
                              void* d_out, int out_size)
{
    const float* query = (const float*)d_in[0];
    const float* key   = (const float*)d_in[1];
    const float* value = (const float*)d_in[2];
    const float* Wq = (const float*)d_in[3];
    const float* bq = (const float*)d_in[4];
    const float* Wk = (const float*)d_in[5];
    const float* bk = (const float*)d_in[6];
    const float* Wv = (const float*)d_in[7];
    const float* bv = (const float*)d_in[8];
    const float* Wo = (const float*)d_in[9];
    const float* bo = (const float*)d_in[10];

    float* out  = (float*)d_out;
    float* attn = out + (size_t)Bn * Sn * Dn;

    float* gQ;  cudaGetSymbolAddress((void**)&gQ,  g_Q);
    float* gK;  cudaGetSymbolAddress((void**)&gK,  g_K);
    float* gV;  cudaGetSymbolAddress((void**)&gV,  g_V);

    const int scoreSmem = (2*128*TSA + 2*64*TSA) * 4;      // 104448 B
    const int bfSmem    = (2*128*TS3 + 2*64*TS3) * 4;      // 55296 B
    const int avSmem    = (2*128*TS3 + 2*32*TSV) * 4;      // 55296 B
    cudaFuncSetAttribute(scores_mma_kernel,
        cudaFuncAttributeMaxDynamicSharedMemorySize, scoreSmem);
    cudaFuncSetAttribute(projv_bf16_kernel,
        cudaFuncAttributeMaxDynamicSharedMemorySize, bfSmem);
    cudaFuncSetAttribute(av_bf16_kernel,
        cudaFuncAttributeMaxDynamicSharedMemorySize, avSmem);
    cudaFuncSetAttribute(outproj_bf16_kernel,
        cudaFuncAttributeMaxDynamicSharedMemorySize, bfSmem);

    dim3 projqkGrid(Dn/128, Mn/128, 2);         // (8, 32, 2) exact fp32
    projqk_kernel<<<projqkGrid, 256>>>(query, key, Wq, Wk, bq, bk, gQ, gK);

    dim3 projvGrid(Dn/64, Mn/128);              // (16, 32) bf16x3
    projv_bf16_kernel<<<projvGrid, 256, bfSmem>>>(value, Wv, bv, gV);

    dim3 scoreGrid(Sn/64, Sn/128, BHn);         // (32, 16, 32) tf32x3
    scores_mma_kernel<<<scoreGrid, 256, scoreSmem>>>(attn);

    topk_softmax_kernel<<<BHn * Sn / TKW, 256>>>(attn);

    dim3 avGrid(Sn/128, BHn);                   // (16, 32) bf16x3
    av_bf16_kernel<<<avGrid, 256, avSmem>>>(attn);

    dim3 outGrid(Dn/64, Mn/128);                // (16, 32) bf16x3
    outproj_bf16_kernel<<<outGrid, 256, bfSmem>>>(Wo, bo, out);
}

// round 14
// speedup vs baseline: 3.2952x; 1.0837x over previous
#include <cuda_runtime.h>
#include <cuda_bf16.h>
#include <cstdint>

#define Bn 2
#define Sn 2048
#define Dn 1024
#define Hn 16
#define HDn 64
#define BHn (Bn*Hn)
#define Mn (Bn*Sn)       // 4096
#define KSEL 1024        // top-k count

// ---- scratch (static device allocations; no cudaMalloc allowed) ----
__device__ float g_Q[Bn*Hn*Sn*HDn];   // (b,h,s,hd)
__device__ float g_K[Bn*Hn*Sn*HDn];
__device__ float g_V[Bn*Hn*Sn*HDn];
__device__ float g_AV[Bn*Hn*Sn*HDn];

// order-preserving float->uint key
__device__ __forceinline__ unsigned fkey(float f){
    unsigned uf = __float_as_uint(f);
    return (uf & 0x80000000u) ? ~uf : (uf | 0x80000000u);
}
__device__ __forceinline__ float finv(unsigned k){
    return __uint_as_float((k & 0x80000000u) ? (k & 0x7FFFFFFFu) : ~k);
}

// ---- tf32 helpers ----
__device__ __forceinline__ void tf32split(float x, unsigned &hi, unsigned &lo){
    unsigned h; asm("cvt.rna.tf32.f32 %0, %1;" : "=r"(h) : "f"(x));
    float hf = __uint_as_float(h);
    asm("cvt.rna.tf32.f32 %0, %1;" : "=r"(lo) : "f"(x - hf));
    hi = h;
}
__device__ __forceinline__ void split4(float4 v, uint4 &hi, uint4 &lo){
    tf32split(v.x, hi.x, lo.x);
    tf32split(v.y, hi.y, lo.y);
    tf32split(v.z, hi.z, lo.z);
    tf32split(v.w, hi.w, lo.w);
}
__device__ __forceinline__ void mma_tf32(float* c, const unsigned* a, const unsigned* b){
    asm volatile("mma.sync.aligned.m16n8k8.row.col.f32.tf32.tf32.f32 "
        "{%0,%1,%2,%3}, {%4,%5,%6,%7}, {%8,%9}, {%0,%1,%2,%3};"
        : "+f"(c[0]), "+f"(c[1]), "+f"(c[2]), "+f"(c[3])
        : "r"(a[0]), "r"(a[1]), "r"(a[2]), "r"(a[3]), "r"(b[0]), "r"(b[1]));
}

// ---- bf16x3 helpers (linear-path GEMMs) ----
__device__ __forceinline__ void bf16x2split(float x, float y, unsigned &hi, unsigned &lo){
    __nv_bfloat16 xh = __float2bfloat16_rn(x);
    __nv_bfloat16 yh = __float2bfloat16_rn(y);
    float xr = x - __bfloat162float(xh);
    float yr = y - __bfloat162float(yh);
    __nv_bfloat16 xl = __float2bfloat16_rn(xr);
    __nv_bfloat16 yl = __float2bfloat16_rn(yr);
    hi = (unsigned)__bfloat16_as_ushort(xh) | ((unsigned)__bfloat16_as_ushort(yh) << 16);
    lo = (unsigned)__bfloat16_as_ushort(xl) | ((unsigned)__bfloat16_as_ushort(yl) << 16);
}
__device__ __forceinline__ void mma_bf16(float* c, const unsigned* a, const unsigned* b){
    asm volatile("mma.sync.aligned.m16n8k16.row.col.f32.bf16.bf16.f32 "
        "{%0,%1,%2,%3}, {%4,%5,%6,%7}, {%8,%9}, {%0,%1,%2,%3};"
        : "+f"(c[0]), "+f"(c[1]), "+f"(c[2]), "+f"(c[3])
        : "r"(a[0]), "r"(a[1]), "r"(a[2]), "r"(a[3]), "r"(b[0]), "r"(b[1]));
}

// tile strides (u32 words)
#define TSA 68   // tf32 64-wide row tiles: conflict-free
#define TS3 36   // bf16 32-word row tiles: conflict-free
#define TSV 72   // bf16 av V pair-row tiles: conflict-free

// tf32x3 warp micro (single accumulator): 32m x 32n, one 64-k chunk
__device__ __forceinline__ void mma_chunk_rowB(
    float acc[2][4][4], const unsigned* Ah, const unsigned* Al,
    const unsigned* Bh, const unsigned* Bl, int mb, int nb, int g, int c)
{
    #pragma unroll
    for (int ks = 0; ks < 8; ks++){
        unsigned ah[2][4], al[2][4];
        #pragma unroll
        for (int mf=0; mf<2; mf++){
            const unsigned* bse = Ah + (mb+mf*16)*TSA + ks*8;
            const unsigned* bsl = Al + (mb+mf*16)*TSA + ks*8;
            ah[mf][0]=bse[ g   *TSA + c  ]; al[mf][0]=bsl[ g   *TSA + c  ];
            ah[mf][1]=bse[(g+8)*TSA + c  ]; al[mf][1]=bsl[(g+8)*TSA + c  ];
            ah[mf][2]=bse[ g   *TSA + c+4]; al[mf][2]=bsl[ g   *TSA + c+4];
            ah[mf][3]=bse[(g+8)*TSA + c+4]; al[mf][3]=bsl[(g+8)*TSA + c+4];
        }
        #pragma unroll
        for (int nf=0; nf<4; nf++){
            unsigned bh_[2], bl_[2];
            const unsigned* bse = Bh + (nb+nf*8+g)*TSA + ks*8;
            const unsigned* bsl = Bl + (nb+nf*8+g)*TSA + ks*8;
            bh_[0]=bse[c]; bh_[1]=bse[c+4];
            bl_[0]=bsl[c]; bl_[1]=bsl[c+4];
            #pragma unroll
            for (int mf=0; mf<2; mf++){
                mma_tf32(acc[mf][nf], ah[mf], bh_);
                mma_tf32(acc[mf][nf], ah[mf], bl_);
                mma_tf32(acc[mf][nf], al[mf], bh_);
            }
        }
    }
}

// tf32x3 warp micro (DUAL accumulators): hh into accH (scalar-like noise),
// cross terms (hi*lo + lo*hi, scaled 2^-11) into accX.
__device__ __forceinline__ void mma_chunk_rowB_dual(
    float accH[2][4][4], float accX[2][4][4],
    const unsigned* Ah, const unsigned* Al,
    const unsigned* Bh, const unsigned* Bl, int mb, int nb, int g, int c)
{
    #pragma unroll
    for (int ks = 0; ks < 8; ks++){
        unsigned ah[2][4], al[2][4];
        #pragma unroll
        for (int mf=0; mf<2; mf++){
            const unsigned* bse = Ah + (mb+mf*16)*TSA + ks*8;
            const unsigned* bsl = Al + (mb+mf*16)*TSA + ks*8;
            ah[mf][0]=bse[ g   *TSA + c  ]; al[mf][0]=bsl[ g   *TSA + c  ];
            ah[mf][1]=bse[(g+8)*TSA + c  ]; al[mf][1]=bsl[(g+8)*TSA + c  ];
            ah[mf][2]=bse[ g   *TSA + c+4]; al[mf][2]=bsl[ g   *TSA + c+4];
            ah[mf][3]=bse[(g+8)*TSA + c+4]; al[mf][3]=bsl[(g+8)*TSA + c+4];
        }
        #pragma unroll
        for (int nf=0; nf<4; nf++){
            unsigned bh_[2], bl_[2];
            const unsigned* bse = Bh + (nb+nf*8+g)*TSA + ks*8;
            const unsigned* bsl = Bl + (nb+nf*8+g)*TSA + ks*8;
            bh_[0]=bse[c]; bh_[1]=bse[c+4];
            bl_[0]=bsl[c]; bl_[1]=bsl[c+4];
            #pragma unroll
            for (int mf=0; mf<2; mf++){
                mma_tf32(accH[mf][nf], ah[mf], bh_);
                mma_tf32(accX[mf][nf], ah[mf], bl_);
                mma_tf32(accX[mf][nf], al[mf], bh_);
            }
        }
    }
}

// bf16x3 warp micro: 32m x 32n, one 64-k chunk
__device__ __forceinline__ void mma_chunk_rowB_bf16(
    float acc[2][4][4], const unsigned* Ah, const unsigned* Al,
    const unsigned* Bh, const unsigned* Bl, int mb, int nb, int g, int c)
{
    #pragma unroll
    for (int ks = 0; ks < 4; ks++){
        unsigned ah[2][4], al[2][4];
        #pragma unroll
        for (int mf=0; mf<2; mf++){
            const unsigned* ph = Ah + (mb+mf*16)*TS3 + ks*8;
            const unsigned* pl = Al + (mb+mf*16)*TS3 + ks*8;
            ah[mf][0]=ph[ g   *TS3 + c  ]; al[mf][0]=pl[ g   *TS3 + c  ];
            ah[mf][1]=ph[(g+8)*TS3 + c  ]; al[mf][1]=pl[(g+8)*TS3 + c  ];
            ah[mf][2]=ph[ g   *TS3 + c+4]; al[mf][2]=pl[ g   *TS3 + c+4];
            ah[mf][3]=ph[(g+8)*TS3 + c+4]; al[mf][3]=pl[(g+8)*TS3 + c+4];
        }
        #pragma unroll
        for (int nf=0; nf<4; nf++){
            const unsigned* ph = Bh + (nb+nf*8+g)*TS3 + ks*8;
            const unsigned* pl = Bl + (nb+nf*8+g)*TS3 + ks*8;
            unsigned bh_[2] = { ph[c], ph[c+4] };
            unsigned bl_[2] = { pl[c], pl[c+4] };
            #pragma unroll
            for (int mf=0; mf<2; mf++){
                mma_bf16(acc[mf][nf], ah[mf], bh_);
                mma_bf16(acc[mf][nf], ah[mf], bl_);
                mma_bf16(acc[mf][nf], al[mf], bh_);
            }
        }
    }
}

// ============================================================
// Kernel 1a: Q/K projections via tf32x3 DUAL-ACC MMA.
// hh terms accumulate alone (scalar-class rounding noise ~1e-6 — the
// level every passing kernel has); cross terms in a separate accumulator.
// blockIdx.z in {0,1} selects Q / K. Block 128m x 64n, k-chunks of 64.
// ============================================================
__global__ __launch_bounds__(256) void projqk_tf32d_kernel(
    const float* __restrict__ Aq, const float* __restrict__ Ak,
    const float* __restrict__ Wq, const float* __restrict__ Wk,
    const float* __restrict__ bq, const float* __restrict__ bk,
    float* __restrict__ Oq, float* __restrict__ Ok)
{
    const float* A; const float* W; const float* bias; float* Out;
    if (blockIdx.z == 0) { A = Aq; W = Wq; bias = bq; Out = Oq; }
    else                 { A = Ak; W = Wk; bias = bk; Out = Ok; }

    extern __shared__ unsigned sm[];
    unsigned* Ah = sm;
    unsigned* Al = Ah + 128*TSA;
    unsigned* Bh = Al + 128*TSA;
    unsigned* Bl = Bh + 64*TSA;

    int m0 = blockIdx.y * 128;
    int n0 = blockIdx.x * 64;
    int tid = threadIdx.x;
    int lane = tid & 31, w = tid >> 5;
    int mb = (w >> 1) * 32, nb = (w & 1) * 32;
    int g = lane >> 2, c = lane & 3;

    float accH[2][4][4], accX[2][4][4];
    #pragma unroll
    for (int mf=0;mf<2;mf++)
        #pragma unroll
        for (int nf=0;nf<4;nf++)
            #pragma unroll
            for (int e=0;e<4;e++){ accH[mf][nf][e]=0.f; accX[mf][nf][e]=0.f; }

    for (int k0 = 0; k0 < Dn; k0 += 64) {
        #pragma unroll
        for (int i = 0; i < 8; i++){
            int idx = tid + i*256;
            int r = idx >> 4, c4 = idx & 15;
            float4 v = *(const float4*)(A + (size_t)(m0+r)*Dn + k0 + c4*4);
            uint4 hi, lo; split4(v, hi, lo);
            *(uint4*)&Ah[r*TSA + c4*4] = hi;
            *(uint4*)&Al[r*TSA + c4*4] = lo;
        }
        #pragma unroll
        for (int i = 0; i < 4; i++){
            int idx = tid + i*256;
            int r = idx >> 4, c4 = idx & 15;
            float4 v = *(const float4*)(W + (size_t)(n0+r)*Dn + k0 + c4*4);
            uint4 hi, lo; split4(v, hi, lo);
            *(uint4*)&Bh[r*TSA + c4*4] = hi;
            *(uint4*)&Bl[r*TSA + c4*4] = lo;
        }
        __syncthreads();
        mma_chunk_rowB_dual(accH, accX, Ah, Al, Bh, Bl, mb, nb, g, c);
        __syncthreads();
    }

    #pragma unroll
    for (int mf=0; mf<2; mf++){
        #pragma unroll
        for (int nf=0; nf<4; nf++){
            int col = n0 + nb + nf*8 + 2*c;
            int h = col >> 6, hd = col & 63;
            float b0 = bias[col], b1 = bias[col+1];
            #pragma unroll
            for (int rr = 0; rr < 2; rr++){
                int row = m0 + mb + mf*16 + g + rr*8;
                int b = row / Sn, s = row % Sn;
                float2 v = make_float2(
                    (accH[mf][nf][2*rr]   + accX[mf][nf][2*rr])   + b0,
                    (accH[mf][nf][2*rr+1] + accX[mf][nf][2*rr+1]) + b1);
                *(float2*)&Out[(((size_t)(b*Hn + h))*Sn + s)*HDn + hd] = v;
            }
        }
    }
}

// ============================================================
// Kernel 1b: V projection via bf16x3 MMA (R13 proven)
// ============================================================
__global__ __launch_bounds__(256) void projv_bf16_kernel(
    const float* __restrict__ A, const float* __restrict__ W,
    const float* __restrict__ bias, float* __restrict__ Out)
{
    extern __shared__ unsigned sm[];
    unsigned* Ah = sm;
    unsigned* Al = Ah + 128*TS3;
    unsigned* Bh = Al + 128*TS3;
    unsigned* Bl = Bh + 64*TS3;

    int m0 = blockIdx.y * 128;
    int n0 = blockIdx.x * 64;
    int tid = threadIdx.x;
    int lane = tid & 31, w = tid >> 5;
    int mb = (w >> 1) * 32, nb = (w & 1) * 32;
    int g = lane >> 2, c = lane & 3;

    float acc[2][4][4];
    #pragma unroll
    for (int mf=0;mf<2;mf++)
        #pragma unroll
        for (int nf=0;nf<4;nf++)
            #pragma unroll
            for (int e=0;e<4;e++) acc[mf][nf][e]=0.f;

    for (int k0 = 0; k0 < Dn; k0 += 64) {
        #pragma unroll
        for (int i = 0; i < 8; i++){
            int idx = tid + i*256;
            int r = idx >> 4, c4 = idx & 15;
            float4 v = *(const float4*)(A + (size_t)(m0+r)*Dn + k0 + c4*4);
            unsigned h0,l0,h1,l1;
            bf16x2split(v.x, v.y, h0, l0);
            bf16x2split(v.z, v.w, h1, l1);
            *(uint2*)&Ah[r*TS3 + c4*2] = make_uint2(h0, h1);
            *(uint2*)&Al[r*TS3 + c4*2] = make_uint2(l0, l1);
        }
        #pragma unroll
        for (int i = 0; i < 4; i++){
            int idx = tid + i*256;
            int r = idx >> 4, c4 = idx & 15;
            float4 v = *(const float4*)(W + (size_t)(n0+r)*Dn + k0 + c4*4);
            unsigned h0,l0,h1,l1;
            bf16x2split(v.x, v.y, h0, l0);
            bf16x2split(v.z, v.w, h1, l1);
            *(uint2*)&Bh[r*TS3 + c4*2] = make_uint2(h0, h1);
            *(uint2*)&Bl[r*TS3 + c4*2] = make_uint2(l0, l1);
        }
        __syncthreads();
        mma_chunk_rowB_bf16(acc, Ah, Al, Bh, Bl, mb, nb, g, c);
        __syncthreads();
    }

    #pragma unroll
    for (int mf=0; mf<2; mf++){
        #pragma unroll
        for (int nf=0; nf<4; nf++){
            int col = n0 + nb + nf*8 + 2*c;
            int h = col >> 6, hd = col & 63;
            float b0 = bias[col], b1 = bias[col+1];
            #pragma unroll
            for (int rr = 0; rr < 2; rr++){
                int row = m0 + mb + mf*16 + g + rr*8;
                int b = row / Sn, s = row % Sn;
                float2 v = make_float2(acc[mf][nf][2*rr] + b0, acc[mf][nf][2*rr+1] + b1);
                *(float2*)&Out[(((size_t)(b*Hn + h))*Sn + s)*HDn + hd] = v;
            }
        }
    }
}

// ============================================================
// Kernel 2: scores via tf32x3 MMA (R11 proven — flip-sensitive, unchanged)
// ============================================================
__global__ __launch_bounds__(256) void scores_mma_kernel(float* __restrict__ attn)
{
    extern __shared__ unsigned sm[];
    unsigned* Ah = sm;
    unsigned* Al = Ah + 128*TSA;
    unsigned* Bh = Al + 128*TSA;
    unsigned* Bl = Bh + 64*TSA;

    int bh = blockIdx.z;
    int q0 = blockIdx.y * 128;
    int n0 = blockIdx.x * 64;
    const float* Qb = g_Q + (size_t)bh*Sn*HDn;
    const float* Kb = g_K + (size_t)bh*Sn*HDn;
    float* Cb = attn + (size_t)bh*Sn*Sn;
    int tid = threadIdx.x;
    int lane = tid & 31, w = tid >> 5;
    int mb = (w >> 1) * 32, nb = (w & 1) * 32;
    int g = lane >> 2, c = lane & 3;

    #pragma unroll
    for (int i = 0; i < 8; i++){
        int idx = tid + i*256;
        int r = idx >> 4, c4 = idx & 15;
        float4 v = *(const float4*)(Qb + (size_t)(q0+r)*HDn + c4*4);
        uint4 hi, lo; split4(v, hi, lo);
        *(uint4*)&Ah[r*TSA + c4*4] = hi;
        *(uint4*)&Al[r*TSA + c4*4] = lo;
    }
    #pragma unroll
    for (int i = 0; i < 4; i++){
        int idx = tid + i*256;
        int r = idx >> 4, c4 = idx & 15;
        float4 v = *(const float4*)(Kb + (size_t)(n0+r)*HDn + c4*4);
        uint4 hi, lo; split4(v, hi, lo);
        *(uint4*)&Bh[r*TSA + c4*4] = hi;
        *(uint4*)&Bl[r*TSA + c4*4] = lo;
    }
    __syncthreads();

    float acc[2][4][4];
    #pragma unroll
    for (int mf=0;mf<2;mf++)
        #pragma unroll
        for (int nf=0;nf<4;nf++)
            #pragma unroll
            for (int e=0;e<4;e++) acc[mf][nf][e]=0.f;

    mma_chunk_rowB(acc, Ah, Al, Bh, Bl, mb, nb, g, c);

    const float scale = 0.125f;
    #pragma unroll
    for (int mf=0; mf<2; mf++){
        #pragma unroll
        for (int nf=0; nf<4; nf++){
            int col = n0 + nb + nf*8 + 2*c;
            #pragma unroll
            for (int rr = 0; rr < 2; rr++){
                int row = q0 + mb + mf*16 + g + rr*8;
                float2 v = make_float2(acc[mf][nf][2*rr]*scale, acc[mf][nf][2*rr+1]*scale);
                *(float2*)(Cb + (size_t)row*Sn + col) = v;
            }
        }
    }
}

// ============================================================
// Kernel 3: per-WARP exact top-k + softmax (R8 proven)
// ============================================================
#define TKW 8
__global__ __launch_bounds__(256) void topk_softmax_kernel(float* __restrict__ attn)
{
    __shared__ unsigned hist[TKW][32*33];

    const int tid  = threadIdx.x;
    const int lane = tid & 31;
    const int w    = tid >> 5;
    const size_t row = (size_t)blockIdx.x * TKW + w;
    float* rowp = attn + row * (size_t)Sn;
    unsigned* H = hist[w];

    unsigned ku[64];
    #pragma unroll
    for (int j = 0; j < 16; j++) {
        float4 v = *(const float4*)(rowp + lane*4 + j*128);
        ku[j*4+0]=fkey(v.x); ku[j*4+1]=fkey(v.y); ku[j*4+2]=fkey(v.z); ku[j*4+3]=fkey(v.w);
    }
    unsigned kmax = 0u;
    #pragma unroll
    for (int e = 0; e < 64; e++) kmax = max(kmax, ku[e]);
    #pragma unroll
    for (int o=16;o>0;o>>=1) kmax = max(kmax, __shfl_xor_sync(0xffffffffu, kmax, o));
    float gmax = finv(kmax);

    unsigned prefix = 0u;
    int r = KSEL;
    #pragma unroll 1
    for (int p = 0; p < 6; p++) {
        const int shift = (p < 5) ? (26 - 6*p) : 0;
        const int nbit  = (p < 5) ? 6 : 2;
        const unsigned binmask = (1u << nbit) - 1u;
        const int sh2 = shift + nbit;
        const unsigned hm = (sh2 >= 32) ? 0u : (0xFFFFFFFFu << sh2);

        unsigned* reg = H + lane*33;
        #pragma unroll
        for (int i = 0; i < 33; i++) reg[i] = 0u;
        __syncwarp();
        #pragma unroll
        for (int e = 0; e < 64; e++) {
            unsigned u = ku[e];
            if ((u & hm) == prefix) {
                unsigned b = (u >> shift) & binmask;
                atomicAdd(&H[lane*33 + (b >> 1)], 1u << (16*(b & 1)));
            }
        }
        __syncwarp();
        unsigned acc = 0u;
        #pragma unroll
        for (int l = 0; l < 32; l++) acc += H[l*33 + lane];
        int cLo = (int)(acc & 0xFFFFu);
        int cHi = (int)(acc >> 16);
        int s   = cLo + cHi;
        int suf = s;
        #pragma unroll
        for (int o = 1; o < 32; o <<= 1) {
            int v = __shfl_down_sync(0xffffffffu, suf, o);
            if (lane + o < 32) suf += v;
        }
        int geL = suf;
        int geH = suf - cLo;
        int geN = suf - s;
        int found = -1, rnew = 0;
        if (geH >= r && geN < r) { found = 2*lane + 1; rnew = r - geN; }
        if (geL >= r && geH < r) { found = 2*lane;     rnew = r - geH; }
        unsigned ball = __ballot_sync(0xffffffffu, found >= 0);
        int src = __ffs(ball) - 1;
        unsigned bsel = __shfl_sync(0xffffffffu, (unsigned)found, src);
        r = __shfl_sync(0xffffffffu, rnew, src);
        prefix |= (bsel << shift);
        __syncwarp();
    }
    unsigned thr = prefix;

    float lsumf = 0.f;
    #pragma unroll
    for (int e = 0; e < 64; e++) {
        unsigned k = ku[e];
        float ex = 0.f;
        if (k >= thr) ex = __expf(finv(k) - gmax);
        ku[e] = __float_as_uint(ex);
        lsumf += ex;
    }
    #pragma unroll
    for (int o=16;o>0;o>>=1) lsumf += __shfl_xor_sync(0xffffffffu, lsumf, o);
    float inv = 1.f / lsumf;
    #pragma unroll
    for (int j = 0; j < 16; j++) {
        float4 v = make_float4(__uint_as_float(ku[j*4+0])*inv,
                               __uint_as_float(ku[j*4+1])*inv,
                               __uint_as_float(ku[j*4+2])*inv,
                               __uint_as_float(ku[j*4+3])*inv);
        *(float4*)(rowp + lane*4 + j*128) = v;
    }
}

// ============================================================
// Kernel 4: AV via bf16x3 MMA (R13 proven)
// ============================================================
__global__ __launch_bounds__(256) void av_bf16_kernel(const float* __restrict__ attn)
{
    extern __shared__ unsigned sm[];
    unsigned* Ah = sm;
    unsigned* Al = Ah + 128*TS3;
    unsigned* Vh = Al + 128*TS3;
    unsigned* Vl = Vh + 32*TSV;

    int bh = blockIdx.y;
    int m0 = blockIdx.x * 128;
    const float* Ab = attn + (size_t)bh*Sn*Sn;
    const float* Vb = g_V + (size_t)bh*Sn*HDn;
    float* Cb = g_AV + (size_t)bh*Sn*HDn;
    int tid = threadIdx.x;
    int lane = tid & 31, w = tid >> 5;
    int mb = (w >> 1) * 32, nb = (w & 1) * 32;
    int g = lane >> 2, c = lane & 3;

    float acc[2][4][4];
    #pragma unroll
    for (int mf=0;mf<2;mf++)
        #pragma unroll
        for (int nf=0;nf<4;nf++)
            #pragma unroll
            for (int e=0;e<4;e++) acc[mf][nf][e]=0.f;

    for (int k0 = 0; k0 < Sn; k0 += 64) {
        #pragma unroll
        for (int i = 0; i < 8; i++){
            int idx = tid + i*256;
            int r = idx >> 4, c4 = idx & 15;
            float4 v = *(const float4*)(Ab + (size_t)(m0+r)*Sn + k0 + c4*4);
            unsigned h0,l0,h1,l1;
            bf16x2split(v.x, v.y, h0, l0);
            bf16x2split(v.z, v.w, h1, l1);
            *(uint2*)&Ah[r*TS3 + c4*2] = make_uint2(h0, h1);
            *(uint2*)&Al[r*TS3 + c4*2] = make_uint2(l0, l1);
        }
        #pragma unroll
        for (int i = 0; i < 2; i++){
            int idx = tid + i*256;
            int pr = idx >> 4, c4 = idx & 15;
            int d = c4 * 4;
            float4 v0 = *(const float4*)(Vb + (size_t)(k0 + 2*pr    )*HDn + d);
            float4 v1 = *(const float4*)(Vb + (size_t)(k0 + 2*pr + 1)*HDn + d);
            unsigned h, l;
            bf16x2split(v0.x, v1.x, h, l); Vh[pr*TSV + d + 0] = h; Vl[pr*TSV + d + 0] = l;
            bf16x2split(v0.y, v1.y, h, l); Vh[pr*TSV + d + 1] = h; Vl[pr*TSV + d + 1] = l;
            bf16x2split(v0.z, v1.z, h, l); Vh[pr*TSV + d + 2] = h; Vl[pr*TSV + d + 2] = l;
            bf16x2split(v0.w, v1.w, h, l); Vh[pr*TSV + d + 3] = h; Vl[pr*TSV + d + 3] = l;
        }
        __syncthreads();

        #pragma unroll
        for (int ks = 0; ks < 4; ks++){
            unsigned ah[2][4], al[2][4];
            #pragma unroll
            for (int mf=0; mf<2; mf++){
                const unsigned* ph = Ah + (mb+mf*16)*TS3 + ks*8;
                const unsigned* pl = Al + (mb+mf*16)*TS3 + ks*8;
                ah[mf][0]=ph[ g   *TS3 + c  ]; al[mf][0]=pl[ g   *TS3 + c  ];
                ah[mf][1]=ph[(g+8)*TS3 + c  ]; al[mf][1]=pl[(g+8)*TS3 + c  ];
                ah[mf][2]=ph[ g   *TS3 + c+4]; al[mf][2]=pl[ g   *TS3 + c+4];
                ah[mf][3]=ph[(g+8)*TS3 + c+4]; al[mf][3]=pl[(g+8)*TS3 + c+4];
            }
            #pragma unroll
            for (int nf=0; nf<4; nf++){
                int d = nb + nf*8 + g;
                unsigned bh_[2], bl_[2];
                bh_[0]=Vh[(ks*8 + c    )*TSV + d]; bl_[0]=Vl[(ks*8 + c    )*TSV + d];
                bh_[1]=Vh[(ks*8 + c + 4)*TSV + d]; bl_[1]=Vl[(ks*8 + c + 4)*TSV + d];
                #pragma unroll
                for (int mf=0; mf<2; mf++){
                    mma_bf16(acc[mf][nf], ah[mf], bh_);
                    mma_bf16(acc[mf][nf], ah[mf], bl_);
                    mma_bf16(acc[mf][nf], al[mf], bh_);
                }
            }
        }
        __syncthreads();
    }

    #pragma unroll
    for (int mf=0; mf<2; mf++){
        #pragma unroll
        for (int nf=0; nf<4; nf++){
            int col = nb + nf*8 + 2*c;
            #pragma unroll
            for (int rr = 0; rr < 2; rr++){
                int row = m0 + mb + mf*16 + g + rr*8;
                float2 v = make_float2(acc[mf][nf][2*rr], acc[mf][nf][2*rr+1]);
                *(float2*)(Cb + (size_t)row*HDn + col) = v;
            }
        }
    }
}

// ============================================================
// Kernel 5: out projection via bf16x3 MMA (R13 proven)
// ============================================================
__global__ __launch_bounds__(256) void outproj_bf16_kernel(
    const float* __restrict__ Wo, const float* __restrict__ bo,
    float* __restrict__ out)
{
    extern __shared__ unsigned sm[];
    unsigned* Ah = sm;
    unsigned* Al = Ah + 128*TS3;
    unsigned* Bh = Al + 128*TS3;
    unsigned* Bl = Bh + 64*TS3;

    int m0 = blockIdx.y * 128;
    int n0 = blockIdx.x * 64;
    int tid = threadIdx.x;
    int lane = tid & 31, w = tid >> 5;
    int mb = (w >> 1) * 32, nb = (w & 1) * 32;
    int g = lane >> 2, c = lane & 3;

    float acc[2][4][4];
    #pragma unroll
    for (int mf=0;mf<2;mf++)
        #pragma unroll
        for (int nf=0;nf<4;nf++)
            #pragma unroll
            for (int e=0;e<4;e++) acc[mf][nf][e]=0.f;

    for (int k0 = 0; k0 < Dn; k0 += 64) {
        int h = k0 >> 6;
        #pragma unroll
        for (int i = 0; i < 8; i++){
            int idx = tid + i*256;
            int r = idx >> 4, c4 = idx & 15;
            int m = m0 + r;
            int b = m / Sn, s = m % Sn;
            float4 v = *(const float4*)(g_AV + (((size_t)(b*Hn + h))*Sn + s)*HDn + c4*4);
            unsigned h0,l0,h1,l1;
            bf16x2split(v.x, v.y, h0, l0);
            bf16x2split(v.z, v.w, h1, l1);
            *(uint2*)&Ah[r*TS3 + c4*2] = make_uint2(h0, h1);
            *(uint2*)&Al[r*TS3 + c4*2] = make_uint2(l0, l1);
        }
        #pragma unroll
        for (int i = 0; i < 4; i++){
            int idx = tid + i*256;
            int r = idx >> 4, c4 = idx & 15;
            float4 v = *(const float4*)(Wo + (size_t)(n0+r)*Dn + k0 + c4*4);
            unsigned h0,l0,h1,l1;
            bf16x2split(v.x, v.y, h0, l0);
            bf16x2split(v.z, v.w, h1, l1);
            *(uint2*)&Bh[r*TS3 + c4*2] = make_uint2(h0, h1);
            *(uint2*)&Bl[r*TS3 + c4*2] = make_uint2(l0, l1);
        }
        __syncthreads();
        mma_chunk_rowB_bf16(acc, Ah, Al, Bh, Bl, mb, nb, g, c);
        __syncthreads();
    }

    #pragma unroll
    for (int mf=0; mf<2; mf++){
        #pragma unroll
        for (int nf=0; nf<4; nf++){
            int col = n0 + nb + nf*8 + 2*c;
            float b0 = bo[col], b1 = bo[col+1];
            #pragma unroll
            for (int rr = 0; rr < 2; rr++){
                int row = m0 + mb + mf*16 + g + rr*8;
                float2 v = make_float2(acc[mf][nf][2*rr] + b0, acc[mf][nf][2*rr+1] + b1);
                *(float2*)(out + (size_t)row*Dn + col) = v;
            }
        }
    }
}

// ============================================================
extern "C" void kernel_launch(void* const* d_in, const int* in_sizes, int n_in,
                              void* d_out, int out_size)
{
    const float* query = (const float*)d_in[0];
    const float* key   = (const float*)d_in[1];
    const float* value = (const float*)d_in[2];
    const float* Wq = (const float*)d_in[3];
    const float* bq = (const float*)d_in[4];
    const float* Wk = (const float*)d_in[5];
    const float* bk = (const float*)d_in[6];
    const float* Wv = (const float*)d_in[7];
    const float* bv = (const float*)d_in[8];
    const float* Wo = (const float*)d_in[9];
    const float* bo = (const float*)d_in[10];

    float* out  = (float*)d_out;
    float* attn = out + (size_t)Bn * Sn * Dn;

    float* gQ;  cudaGetSymbolAddress((void**)&gQ,  g_Q);
    float* gK;  cudaGetSymbolAddress((void**)&gK,  g_K);
    float* gV;  cudaGetSymbolAddress((void**)&gV,  g_V);

    const int scoreSmem = (2*128*TSA + 2*64*TSA) * 4;      // 104448 B
    const int bfSmem    = (2*128*TS3 + 2*64*TS3) * 4;      // 55296 B
    const int avSmem    = (2*128*TS3 + 2*32*TSV) * 4;      // 55296 B
    cudaFuncSetAttribute(projqk_tf32d_kernel,
        cudaFuncAttributeMaxDynamicSharedMemorySize, scoreSmem);
    cudaFuncSetAttribute(scores_mma_kernel,
        cudaFuncAttributeMaxDynamicSharedMemorySize, scoreSmem);
    cudaFuncSetAttribute(projv_bf16_kernel,
        cudaFuncAttributeMaxDynamicSharedMemorySize, bfSmem);
    cudaFuncSetAttribute(av_bf16_kernel,
        cudaFuncAttributeMaxDynamicSharedMemorySize, avSmem);
    cudaFuncSetAttribute(outproj_bf16_kernel,
        cudaFuncAttributeMaxDynamicSharedMemorySize, bfSmem);

    dim3 projqkGrid(Dn/64, Mn/128, 2);          // (16, 32, 2) tf32x3 dual-acc
    projqk_tf32d_kernel<<<projqkGrid, 256, scoreSmem>>>(query, key, Wq, Wk, bq, bk, gQ, gK);

    dim3 projvGrid(Dn/64, Mn/128);              // (16, 32) bf16x3
    projv_bf16_kernel<<<projvGrid, 256, bfSmem>>>(value, Wv, bv, gV);

    dim3 scoreGrid(Sn/64, Sn/128, BHn);         // (32, 16, 32) tf32x3
    scores_mma_kernel<<<scoreGrid, 256, scoreSmem>>>(attn);

    topk_softmax_kernel<<<BHn * Sn / TKW, 256>>>(attn);

    dim3 avGrid(Sn/128, BHn);                   // (16, 32) bf16x3
    av_bf16_kernel<<<avGrid, 256, avSmem>>>(attn);

    dim3 outGrid(Dn/64, Mn/128);                // (16, 32) bf16x3
    outproj_bf16_kernel<<<outGrid, 256, bfSmem>>>(Wo, bo, out);
}